// round 1
// baseline (speedup 1.0000x reference)
#include <cuda_runtime.h>

#define T_LEN 16384
#define BATCH 4
#define CRES 128
#define CSKIP 256
#define TT 128              // time tile per CTA
#define RS 132              // padded row stride for activation tiles (floats)
#define WS 129              // padded row stride for weight staging (floats)
#define NBLK 40
#define SKIPLEN 4096
#define SKIPSTART (T_LEN - SKIPLEN)

// Ping-pong residual activation buffers (33.5 MB each)
__device__ float g_bufA[BATCH * CRES * T_LEN];
__device__ float g_bufB[BATCH * CRES * T_LEN];

__global__ void __launch_bounds__(256, 1)
wnet_block(const float* __restrict__ in, float* __restrict__ resout,
           const float* __restrict__ wd, const float* __restrict__ wr,
           const float* __restrict__ wsk, float* __restrict__ skipout,
           int dil)
{
    extern __shared__ float sm[];
    float* Xc = sm;                 // [128][RS]  current tile
    float* G  = sm + CRES * RS;     // [128][RS]  first Xd (shifted), then gated
    float* WB = sm + 2 * CRES * RS; // weight staging (<= 4224 floats)

    const int tid = threadIdx.x;
    const int tx  = tid & 15;       // 16 time groups  (x8 = 128 t)
    const int ty  = tid >> 4;       // 16 out groups   (x8 = 128 o)
    const int b   = blockIdx.y;
    const int t0  = blockIdx.x * TT;
    const int ob  = ty * 8;
    const int tb  = tx * 8;

    const float* src = in + (size_t)b * CRES * T_LEN;

    // ---- Load Xc (aligned float4) and Xd (shifted by dil, zero-padded) ----
    for (int e = tid; e < CRES * (TT / 4); e += 256) {
        int row = e >> 5;           // 32 float4 per row
        int c4  = e & 31;
        const float* p = src + (size_t)row * T_LEN + t0 + c4 * 4;
        float4 v = *reinterpret_cast<const float4*>(p);
        *reinterpret_cast<float4*>(Xc + row * RS + c4 * 4) = v;
        int ts = t0 + c4 * 4 - dil;
        float4 vd;
        vd.x = (ts + 0 >= 0) ? p[0 - dil] : 0.f;
        vd.y = (ts + 1 >= 0) ? p[1 - dil] : 0.f;
        vd.z = (ts + 2 >= 0) ? p[2 - dil] : 0.f;
        vd.w = (ts + 3 >= 0) ? p[3 - dil] : 0.f;
        *reinterpret_cast<float4*>(G + row * RS + c4 * 4) = vd;
    }

    float acc[8][8];
    #pragma unroll
    for (int i = 0; i < 8; ++i)
        #pragma unroll
        for (int j = 0; j < 8; ++j) acc[i][j] = 0.f;

    // ================= Phase 1: h = W0 @ Xd + W1 @ Xc =================
    for (int cc = 0; cc < CRES; cc += 16) {
        __syncthreads();
        #pragma unroll
        for (int it = 0; it < 16; ++it) {
            int e  = tid + it * 256;
            int o  = e >> 5;
            int r  = e & 31;
            int cl = r >> 1;
            int k  = r & 1;
            WB[(cl * 2 + k) * WS + o] = wd[(o * CRES + cc + cl) * 2 + k];
        }
        __syncthreads();
        #pragma unroll 4
        for (int cl = 0; cl < 16; ++cl) {
            const float* gr = G  + (cc + cl) * RS + tb;
            const float* xr = Xc + (cc + cl) * RS + tb;
            float4 d0 = *reinterpret_cast<const float4*>(gr);
            float4 d1 = *reinterpret_cast<const float4*>(gr + 4);
            float4 c0 = *reinterpret_cast<const float4*>(xr);
            float4 c1 = *reinterpret_cast<const float4*>(xr + 4);
            #pragma unroll
            for (int i = 0; i < 8; ++i) {
                float w0 = WB[(cl * 2 + 0) * WS + ob + i];
                float w1 = WB[(cl * 2 + 1) * WS + ob + i];
                float* a = acc[i];
                a[0] = fmaf(w0, d0.x, fmaf(w1, c0.x, a[0]));
                a[1] = fmaf(w0, d0.y, fmaf(w1, c0.y, a[1]));
                a[2] = fmaf(w0, d0.z, fmaf(w1, c0.z, a[2]));
                a[3] = fmaf(w0, d0.w, fmaf(w1, c0.w, a[3]));
                a[4] = fmaf(w0, d1.x, fmaf(w1, c1.x, a[4]));
                a[5] = fmaf(w0, d1.y, fmaf(w1, c1.y, a[5]));
                a[6] = fmaf(w0, d1.z, fmaf(w1, c1.z, a[6]));
                a[7] = fmaf(w0, d1.w, fmaf(w1, c1.w, a[7]));
            }
        }
    }

    // ---- gated = tanh(h) * sigmoid(h); overwrite G ----
    __syncthreads();   // all phase-1 reads of G(Xd) done
    #pragma unroll
    for (int i = 0; i < 8; ++i) {
        float g[8];
        #pragma unroll
        for (int j = 0; j < 8; ++j) {
            float h = acc[i][j];
            h = fminf(fmaxf(h, -30.f), 30.f);
            float e1 = __expf(-h);
            float e2 = e1 * e1;
            float th = (1.f - e2) / (1.f + e2);
            float sg = 1.f / (1.f + e1);
            g[j] = th * sg;
        }
        *reinterpret_cast<float4*>(G + (ob + i) * RS + tb)     = make_float4(g[0], g[1], g[2], g[3]);
        *reinterpret_cast<float4*>(G + (ob + i) * RS + tb + 4) = make_float4(g[4], g[5], g[6], g[7]);
    }

    // ================= Phase 2: out = Wr @ G + Xc =================
    #pragma unroll
    for (int i = 0; i < 8; ++i)
        #pragma unroll
        for (int j = 0; j < 8; ++j) acc[i][j] = 0.f;

    for (int cc = 0; cc < CRES; cc += 16) {
        __syncthreads();
        #pragma unroll
        for (int it = 0; it < 8; ++it) {
            int e  = tid + it * 256;
            int o  = e >> 4;
            int cl = e & 15;
            WB[cl * WS + o] = wr[o * CRES + cc + cl];
        }
        __syncthreads();
        #pragma unroll 4
        for (int cl = 0; cl < 16; ++cl) {
            const float* gr = G + (cc + cl) * RS + tb;
            float4 g0 = *reinterpret_cast<const float4*>(gr);
            float4 g1 = *reinterpret_cast<const float4*>(gr + 4);
            #pragma unroll
            for (int i = 0; i < 8; ++i) {
                float w = WB[cl * WS + ob + i];
                float* a = acc[i];
                a[0] = fmaf(w, g0.x, a[0]); a[1] = fmaf(w, g0.y, a[1]);
                a[2] = fmaf(w, g0.z, a[2]); a[3] = fmaf(w, g0.w, a[3]);
                a[4] = fmaf(w, g1.x, a[4]); a[5] = fmaf(w, g1.y, a[5]);
                a[6] = fmaf(w, g1.z, a[6]); a[7] = fmaf(w, g1.w, a[7]);
            }
        }
    }
    {
        float* dst = resout + (size_t)b * CRES * T_LEN + t0;
        #pragma unroll
        for (int i = 0; i < 8; ++i) {
            const float* xr = Xc + (ob + i) * RS + tb;
            float4 r0, r1;
            r0.x = acc[i][0] + xr[0]; r0.y = acc[i][1] + xr[1];
            r0.z = acc[i][2] + xr[2]; r0.w = acc[i][3] + xr[3];
            r1.x = acc[i][4] + xr[4]; r1.y = acc[i][5] + xr[5];
            r1.z = acc[i][6] + xr[6]; r1.w = acc[i][7] + xr[7];
            float* q = dst + (size_t)(ob + i) * T_LEN + tb;
            *reinterpret_cast<float4*>(q)     = r0;
            *reinterpret_cast<float4*>(q + 4) = r1;
        }
    }

    // ================= Phase 3: skip = Wskip @ G (last 4096 only) =================
    if (t0 >= SKIPSTART) {
        float* sdst = skipout + (size_t)b * CSKIP * SKIPLEN + (t0 - SKIPSTART);
        for (int half = 0; half < 2; ++half) {
            #pragma unroll
            for (int i = 0; i < 8; ++i)
                #pragma unroll
                for (int j = 0; j < 8; ++j) acc[i][j] = 0.f;

            for (int cc = 0; cc < CRES; cc += 16) {
                __syncthreads();
                #pragma unroll
                for (int it = 0; it < 8; ++it) {
                    int e  = tid + it * 256;
                    int o  = e >> 4;
                    int cl = e & 15;
                    WB[cl * WS + o] = wsk[(half * 128 + o) * CRES + cc + cl];
                }
                __syncthreads();
                #pragma unroll 4
                for (int cl = 0; cl < 16; ++cl) {
                    const float* gr = G + (cc + cl) * RS + tb;
                    float4 g0 = *reinterpret_cast<const float4*>(gr);
                    float4 g1 = *reinterpret_cast<const float4*>(gr + 4);
                    #pragma unroll
                    for (int i = 0; i < 8; ++i) {
                        float w = WB[cl * WS + ob + i];
                        float* a = acc[i];
                        a[0] = fmaf(w, g0.x, a[0]); a[1] = fmaf(w, g0.y, a[1]);
                        a[2] = fmaf(w, g0.z, a[2]); a[3] = fmaf(w, g0.w, a[3]);
                        a[4] = fmaf(w, g1.x, a[4]); a[5] = fmaf(w, g1.y, a[5]);
                        a[6] = fmaf(w, g1.z, a[6]); a[7] = fmaf(w, g1.w, a[7]);
                    }
                }
            }
            #pragma unroll
            for (int i = 0; i < 8; ++i) {
                int row = half * 128 + ob + i;
                float* q = sdst + (size_t)row * SKIPLEN + tb;
                *reinterpret_cast<float4*>(q)     = make_float4(acc[i][0], acc[i][1], acc[i][2], acc[i][3]);
                *reinterpret_cast<float4*>(q + 4) = make_float4(acc[i][4], acc[i][5], acc[i][6], acc[i][7]);
            }
        }
    }
}

extern "C" void kernel_launch(void* const* d_in, const int* in_sizes, int n_in,
                              void* d_out, int out_size)
{
    const float* x      = (const float*)d_in[0];
    const float* w_dil  = (const float*)d_in[1];
    const float* w_res  = (const float*)d_in[2];
    const float* w_skip = (const float*)d_in[3];
    float* out = (float*)d_out;

    float *pA, *pB;
    cudaGetSymbolAddress((void**)&pA, g_bufA);
    cudaGetSymbolAddress((void**)&pB, g_bufB);
    float* bufs[2] = {pA, pB};

    const size_t SMEM = (size_t)(2 * CRES * RS + 4224) * sizeof(float);
    cudaFuncSetAttribute(wnet_block, cudaFuncAttributeMaxDynamicSharedMemorySize, (int)SMEM);

    dim3 grid(T_LEN / TT, BATCH), blk(256);
    for (int i = 0; i < NBLK; ++i) {
        const float* src = (i == 0) ? x : bufs[(i + 1) & 1];
        float* ro = bufs[i & 1];
        int dil = 1 << (i % 10);
        wnet_block<<<grid, blk, SMEM>>>(
            src, ro,
            w_dil  + (size_t)i * CRES * CRES * 2,
            w_res  + (size_t)i * CRES * CRES,
            w_skip + (size_t)i * CSKIP * CRES,
            out    + (size_t)i * BATCH * CSKIP * SKIPLEN,
            dil);
    }
}

// round 3
// speedup vs baseline: 1.8479x; 1.8479x over previous
#include <cuda_runtime.h>
#include <cuda_bf16.h>
#include <cstdint>

#define T_LEN 16384
#define BATCH 4
#define CRES 128
#define NBLK 40
#define SKIPLEN 4096
#define SKIPSTART (T_LEN - SKIPLEN)

#define PADB 272            // bytes per SMEM row (136 bf16 slots, 128 used)
#define SLOT 34816          // 128 * 272
#define SM_XDHI 0
#define SM_XDLO (1*SLOT)
#define SM_XCHI (2*SLOT)
#define SM_XCLO (3*SLOT)
#define SM_WHI  (4*SLOT)
#define SM_WLO  (5*SLOT)
#define SM_TOTAL (6*SLOT)   // 208896 B
#define SM_BOUNCE SM_XCHI   // fp32 bounce 128 x BSTR (reuses XC slots in skip phase)
#define BSTR 133

// ---------------- device scratch ----------------
__device__ float g_actA[(size_t)BATCH * T_LEN * CRES];
__device__ float g_actB[(size_t)BATCH * T_LEN * CRES];
// per block: 10 images of 128x128 bf16, row-major [o][k]:
// [0]=wd0hi [1]=wd0lo [2]=wd1hi [3]=wd1lo [4]=wreshi [5]=wreslo
// [6]=wskAhi [7]=wskAlo [8]=wskBhi [9]=wskBlo
__device__ __align__(16) __nv_bfloat16 g_wimg[(size_t)NBLK * 10 * 16384];

// ---------------- helpers ----------------
__device__ __forceinline__ uint32_t smem_u32(const void* p) {
    uint32_t a;
    asm("{ .reg .u64 t; cvta.to.shared.u64 t, %1; cvt.u32.u64 %0, t; }" : "=r"(a) : "l"(p));
    return a;
}

__device__ __forceinline__ void ldsm4(uint32_t* r, uint32_t addr) {
    asm volatile("ldmatrix.sync.aligned.m8n8.x4.shared.b16 {%0,%1,%2,%3}, [%4];"
                 : "=r"(r[0]), "=r"(r[1]), "=r"(r[2]), "=r"(r[3]) : "r"(addr));
}

__device__ __forceinline__ void mma16816(float* d, const uint32_t* a, const uint32_t* b) {
    asm volatile("mma.sync.aligned.m16n8k16.row.col.f32.bf16.bf16.f32 "
                 "{%0,%1,%2,%3},{%4,%5,%6,%7},{%8,%9},{%0,%1,%2,%3};"
                 : "+f"(d[0]), "+f"(d[1]), "+f"(d[2]), "+f"(d[3])
                 : "r"(a[0]), "r"(a[1]), "r"(a[2]), "r"(a[3]), "r"(b[0]), "r"(b[1]));
}

__device__ __forceinline__ void split2(float x0, float x1, uint32_t& hi, uint32_t& lo) {
    __nv_bfloat16 h0 = __float2bfloat16(x0), h1 = __float2bfloat16(x1);
    float r0 = x0 - __bfloat162float(h0), r1 = x1 - __bfloat162float(h1);
    __nv_bfloat16 l0 = __float2bfloat16(r0), l1 = __float2bfloat16(r1);
    hi = (uint32_t)__bfloat16_as_ushort(h0) | ((uint32_t)__bfloat16_as_ushort(h1) << 16);
    lo = (uint32_t)__bfloat16_as_ushort(l0) | ((uint32_t)__bfloat16_as_ushort(l1) << 16);
}

__device__ __forceinline__ float gate_fn(float h) {
    h = fminf(fmaxf(h, -30.f), 30.f);
    float e1 = __expf(-h);
    float e2 = e1 * e1;
    return ((1.f - e2) / (1.f + e2)) * (1.f / (1.f + e1));
}

// ---------------- pre-pass kernels ----------------
__global__ void transpose_x(const float* __restrict__ x, float* __restrict__ xt) {
    __shared__ float tile[32][33];
    int b = blockIdx.z, c0 = blockIdx.y * 32, t0 = blockIdx.x * 32;
    int lx = threadIdx.x, ly = threadIdx.y;
    #pragma unroll
    for (int i = 0; i < 32; i += 8)
        tile[ly + i][lx] = x[((size_t)b * CRES + c0 + ly + i) * T_LEN + t0 + lx];
    __syncthreads();
    #pragma unroll
    for (int i = 0; i < 32; i += 8)
        xt[((size_t)b * T_LEN + t0 + ly + i) * CRES + c0 + lx] = tile[lx][ly + i];
}

__global__ void prep_weights(const float* __restrict__ wd, const float* __restrict__ wr,
                             const float* __restrict__ wsk, __nv_bfloat16* __restrict__ img) {
    int blk = blockIdx.x, m = blockIdx.y;
    for (int e = threadIdx.x; e < 16384; e += 256) {
        int o = e >> 7, k = e & 127;
        float v;
        if      (m == 0) v = wd[((size_t)blk * 16384 + o * 128 + k) * 2 + 0];
        else if (m == 1) v = wd[((size_t)blk * 16384 + o * 128 + k) * 2 + 1];
        else if (m == 2) v = wr[(size_t)blk * 16384 + o * 128 + k];
        else if (m == 3) v = wsk[(size_t)blk * 32768 + o * 128 + k];
        else             v = wsk[(size_t)blk * 32768 + (o + 128) * 128 + k];
        __nv_bfloat16 hi = __float2bfloat16(v);
        float rem = v - __bfloat162float(hi);
        __nv_bfloat16 lo = __float2bfloat16(rem);
        size_t base = ((size_t)blk * 10 + (size_t)m * 2) * 16384;
        img[base + e] = hi;
        img[base + 16384 + e] = lo;
    }
}

// ---------------- main block kernel ----------------
__global__ void __launch_bounds__(256, 1)
wnet_mma(const float* __restrict__ in, float* __restrict__ resout,
         const __nv_bfloat16* __restrict__ img, float* __restrict__ skipout, int dil)
{
    extern __shared__ char smem[];
    const uint32_t sb = smem_u32(smem);
    const int tid = threadIdx.x;
    const int lane = tid & 31, wid = tid >> 5;
    const int wm = wid & 3;        // M group (32 rows)
    const int wn = wid >> 2;       // N group (64 cols)
    const int b = blockIdx.y, t0 = blockIdx.x * 128;

    // per-lane ldmatrix address offsets (bytes)
    const uint32_t a_off = (uint32_t)(lane & 15) * PADB + (uint32_t)(lane >> 4) * 16;
    const uint32_t b_off = (uint32_t)((lane & 7) + ((lane >> 4) << 3)) * PADB
                         + (uint32_t)((lane >> 3) & 1) * 16;

    const float* src = in + (size_t)b * T_LEN * CRES;

    // ---- weight pair loader (hi+lo images -> padded SMEM) ----
    auto load_w = [&](int imgidx) {
        const uint4* ghi = (const uint4*)(img + (size_t)imgidx * 16384);
        const uint4* glo = (const uint4*)(img + (size_t)(imgidx + 1) * 16384);
        #pragma unroll
        for (int e0 = 0; e0 < 2048; e0 += 256) {
            int e = e0 + tid;
            int row = e >> 4, c = e & 15;
            *(uint4*)(smem + SM_WHI + row * PADB + c * 16) = ghi[e];
            *(uint4*)(smem + SM_WLO + row * PADB + c * 16) = glo[e];
        }
    };

    // ---- activation tile load + bf16 split ----
    auto load_split = [&](int smhi, int smlo, bool shifted) {
        int row = tid >> 1, half = tid & 1;
        int ts = shifted ? (t0 + row - dil) : (t0 + row);
        bool valid = ts >= 0;
        const float* rp = src + (size_t)(valid ? ts : 0) * CRES + half * 64;
        char* dh = smem + smhi + row * PADB + half * 128;
        char* dl = smem + smlo + row * PADB + half * 128;
        #pragma unroll
        for (int j = 0; j < 16; ++j) {
            float4 v = valid ? *(const float4*)(rp + j * 4) : make_float4(0.f, 0.f, 0.f, 0.f);
            uint32_t h0, l0, h1, l1;
            split2(v.x, v.y, h0, l0);
            split2(v.z, v.w, h1, l1);
            *(uint32_t*)(dh + j * 8)     = h0;
            *(uint32_t*)(dh + j * 8 + 4) = h1;
            *(uint32_t*)(dl + j * 8)     = l0;
            *(uint32_t*)(dl + j * 8 + 4) = l1;
        }
    };

    // ---- one K=128 GEMM term: acc += A(smem) x W(smem)^T ----
    auto gemm_term = [&](float (&acc)[2][8][4], uint32_t aOff, uint32_t wOff) {
        uint32_t Abase = sb + aOff + (uint32_t)wm * 32 * PADB + a_off;
        uint32_t Wbase = sb + wOff + (uint32_t)wn * 64 * PADB + b_off;
        #pragma unroll
        for (int k0 = 0; k0 < 8; ++k0) {
            uint32_t a[2][4], bb[4][4];
            ldsm4(a[0], Abase + k0 * 32);
            ldsm4(a[1], Abase + 16 * PADB + k0 * 32);
            #pragma unroll
            for (int n2 = 0; n2 < 4; ++n2)
                ldsm4(bb[n2], Wbase + n2 * 16 * PADB + k0 * 32);
            #pragma unroll
            for (int mt = 0; mt < 2; ++mt)
                #pragma unroll
                for (int nt = 0; nt < 8; ++nt)
                    mma16816(acc[mt][nt], a[mt], &bb[nt >> 1][(nt & 1) * 2]);
        }
    };

    // 3-term bf16-split GEMM: hi*Whi + hi*Wlo + lo*Whi
    auto gemm3 = [&](float (&acc)[2][8][4], uint32_t aHi, uint32_t aLo) {
        const uint32_t ta[3] = {aHi, aHi, aLo};
        const uint32_t tw[3] = {SM_WHI, SM_WLO, SM_WHI};
        #pragma unroll 1
        for (int t = 0; t < 3; ++t) gemm_term(acc, ta[t], tw[t]);
    };

    float acc[2][8][4];
    auto zero_acc = [&]() {
        #pragma unroll
        for (int mt = 0; mt < 2; ++mt)
            #pragma unroll
            for (int nt = 0; nt < 8; ++nt)
                #pragma unroll
                for (int j = 0; j < 4; ++j) acc[mt][nt][j] = 0.f;
    };

    // ================= phase 1: h = Wd0 @ Xd + Wd1 @ Xc =================
    load_w(0);                                   // wd0 hi/lo
    load_split(SM_XCHI, SM_XCLO, false);
    load_split(SM_XDHI, SM_XDLO, true);
    __syncthreads();

    zero_acc();
    gemm3(acc, SM_XDHI, SM_XDLO);
    __syncthreads();                             // done reading W(wd0)
    load_w(2);                                   // wd1 hi/lo
    __syncthreads();
    gemm3(acc, SM_XCHI, SM_XCLO);
    __syncthreads();                             // done reading XD & W

    // ---- gate in registers -> G (bf16 split) into XD slots ----
    #pragma unroll
    for (int mt = 0; mt < 2; ++mt)
        #pragma unroll
        for (int nt = 0; nt < 8; ++nt) {
            int r0 = wm * 32 + mt * 16 + (lane >> 2);
            int c  = wn * 64 + nt * 8 + (lane & 3) * 2;
            #pragma unroll
            for (int h = 0; h < 2; ++h) {
                float g0 = gate_fn(acc[mt][nt][h * 2 + 0]);
                float g1 = gate_fn(acc[mt][nt][h * 2 + 1]);
                uint32_t hi, lo;
                split2(g0, g1, hi, lo);
                int r = r0 + h * 8;
                *(uint32_t*)(smem + SM_XDHI + r * PADB + c * 2) = hi;
                *(uint32_t*)(smem + SM_XDLO + r * PADB + c * 2) = lo;
            }
        }
    load_w(4);                                   // wres hi/lo
    __syncthreads();

    // ================= phase 2: res = Wres @ G; out = res + Xc =================
    zero_acc();
    gemm3(acc, SM_XDHI, SM_XDLO);
    {
        float* dst = resout + ((size_t)b * T_LEN + t0) * CRES;
        const float* xc = src + (size_t)t0 * CRES;
        #pragma unroll
        for (int mt = 0; mt < 2; ++mt)
            #pragma unroll
            for (int nt = 0; nt < 8; ++nt) {
                int c = wn * 64 + nt * 8 + (lane & 3) * 2;
                #pragma unroll
                for (int h = 0; h < 2; ++h) {
                    int r = wm * 32 + mt * 16 + (lane >> 2) + h * 8;
                    float2 x = *(const float2*)(xc + (size_t)r * CRES + c);
                    float2 o;
                    o.x = acc[mt][nt][h * 2 + 0] + x.x;
                    o.y = acc[mt][nt][h * 2 + 1] + x.y;
                    *(float2*)(dst + (size_t)r * CRES + c) = o;
                }
            }
    }
    __syncthreads();                             // done reading W(wres) before overwrite

    // ================= phase 3: skip = Wskip @ G (last 4096 t only) =================
    if (t0 >= SKIPSTART) {
        float* bn = (float*)(smem + SM_BOUNCE);
        float* sbase = skipout + (size_t)b * 256 * SKIPLEN + (t0 - SKIPSTART);
        #pragma unroll 1
        for (int half = 0; half < 2; ++half) {
            load_w(6 + half * 2);
            __syncthreads();
            zero_acc();
            gemm3(acc, SM_XDHI, SM_XDLO);
            // stage acc -> bounce [t][o], stride BSTR floats
            #pragma unroll
            for (int mt = 0; mt < 2; ++mt)
                #pragma unroll
                for (int nt = 0; nt < 8; ++nt) {
                    int c = wn * 64 + nt * 8 + (lane & 3) * 2;
                    #pragma unroll
                    for (int h = 0; h < 2; ++h) {
                        int r = wm * 32 + mt * 16 + (lane >> 2) + h * 8;
                        bn[r * BSTR + c]     = acc[mt][nt][h * 2 + 0];
                        bn[r * BSTR + c + 1] = acc[mt][nt][h * 2 + 1];
                    }
                }
            __syncthreads();
            // coalesced write: per warp-iter, 4 o-rows x 128 t
            #pragma unroll 1
            for (int it = 0; it < 4; ++it) {
                int o = it * 32 + wid * 4 + (lane >> 3);
                float* gdst = sbase + (size_t)(half * 128 + o) * SKIPLEN;
                #pragma unroll
                for (int j = 0; j < 4; ++j) {
                    int tt = (lane & 7) * 4 + j * 32;
                    float4 v;
                    v.x = bn[(tt + 0) * BSTR + o];
                    v.y = bn[(tt + 1) * BSTR + o];
                    v.z = bn[(tt + 2) * BSTR + o];
                    v.w = bn[(tt + 3) * BSTR + o];
                    *(float4*)(gdst + tt) = v;
                }
            }
            __syncthreads();
        }
    }
}

// ---------------- host ----------------
extern "C" void kernel_launch(void* const* d_in, const int* in_sizes, int n_in,
                              void* d_out, int out_size)
{
    const float* x      = (const float*)d_in[0];
    const float* w_dil  = (const float*)d_in[1];
    const float* w_res  = (const float*)d_in[2];
    const float* w_skip = (const float*)d_in[3];
    float* out = (float*)d_out;

    float *pA, *pB;
    __nv_bfloat16* pimg;
    cudaGetSymbolAddress((void**)&pA, g_actA);
    cudaGetSymbolAddress((void**)&pB, g_actB);
    cudaGetSymbolAddress((void**)&pimg, g_wimg);

    cudaFuncSetAttribute(wnet_mma, cudaFuncAttributeMaxDynamicSharedMemorySize, SM_TOTAL);

    transpose_x<<<dim3(T_LEN / 32, CRES / 32, BATCH), dim3(32, 8)>>>(x, pA);
    prep_weights<<<dim3(NBLK, 5), 256>>>(w_dil, w_res, w_skip, pimg);

    for (int i = 0; i < NBLK; ++i) {
        const float* srcp = (i & 1) ? pB : pA;
        float* dstp       = (i & 1) ? pA : pB;
        wnet_mma<<<dim3(T_LEN / 128, BATCH), 256, SM_TOTAL>>>(
            srcp, dstp,
            pimg + (size_t)i * 10 * 16384,
            out + (size_t)i * BATCH * 256 * SKIPLEN,
            1 << (i % 10));
    }
}

// round 4
// speedup vs baseline: 2.1612x; 1.1695x over previous
#include <cuda_runtime.h>
#include <cuda_bf16.h>
#include <cstdint>

#define T_LEN 16384
#define BATCH 4
#define CRES 128
#define NBLK 40
#define SKIPLEN 4096
#define SKIPSTART (T_LEN - SKIPLEN)

#define THREADS 512
#define PADB 272            // bytes per SMEM row (136 bf16 slots, 128 used)
#define SLOT 34816          // 128 * 272
#define SM_XDHI 0
#define SM_XDLO (1*SLOT)
#define SM_XCHI (2*SLOT)
#define SM_XCLO (3*SLOT)
#define SM_WHI  (4*SLOT)
#define SM_WLO  (5*SLOT)
#define SM_TOTAL (6*SLOT)   // 208896 B
#define SM_BOUNCE SM_XCHI   // fp32 bounce 128 x BSTR (XC slots free in skip phase)
#define BSTR 133

// ---------------- device scratch ----------------
__device__ float g_actA[(size_t)BATCH * T_LEN * CRES];
__device__ float g_actB[(size_t)BATCH * T_LEN * CRES];
// per block: 10 images of 128x128 bf16, row-major [o][k]:
// [0]=wd0hi [1]=wd0lo [2]=wd1hi [3]=wd1lo [4]=wreshi [5]=wreslo
// [6]=wskAhi [7]=wskAlo [8]=wskBhi [9]=wskBlo
__device__ __align__(16) __nv_bfloat16 g_wimg[(size_t)NBLK * 10 * 16384];

// ---------------- helpers ----------------
__device__ __forceinline__ uint32_t smem_u32(const void* p) {
    uint32_t a;
    asm("{ .reg .u64 t; cvta.to.shared.u64 t, %1; cvt.u32.u64 %0, t; }" : "=r"(a) : "l"(p));
    return a;
}
__device__ __forceinline__ void ldsm4(uint32_t* r, uint32_t addr) {
    asm volatile("ldmatrix.sync.aligned.m8n8.x4.shared.b16 {%0,%1,%2,%3}, [%4];"
                 : "=r"(r[0]), "=r"(r[1]), "=r"(r[2]), "=r"(r[3]) : "r"(addr));
}
__device__ __forceinline__ void mma16816(float* d, const uint32_t* a, const uint32_t* b) {
    asm volatile("mma.sync.aligned.m16n8k16.row.col.f32.bf16.bf16.f32 "
                 "{%0,%1,%2,%3},{%4,%5,%6,%7},{%8,%9},{%0,%1,%2,%3};"
                 : "+f"(d[0]), "+f"(d[1]), "+f"(d[2]), "+f"(d[3])
                 : "r"(a[0]), "r"(a[1]), "r"(a[2]), "r"(a[3]), "r"(b[0]), "r"(b[1]));
}
__device__ __forceinline__ void cpa16(uint32_t dst, const void* src) {
    asm volatile("cp.async.cg.shared.global [%0], [%1], 16;" :: "r"(dst), "l"(src));
}
#define CP_COMMIT() asm volatile("cp.async.commit_group;" ::: "memory")
#define CP_WAIT0()  asm volatile("cp.async.wait_group 0;" ::: "memory")

__device__ __forceinline__ void split2(float x0, float x1, uint32_t& hi, uint32_t& lo) {
    __nv_bfloat16 h0 = __float2bfloat16(x0), h1 = __float2bfloat16(x1);
    float r0 = x0 - __bfloat162float(h0), r1 = x1 - __bfloat162float(h1);
    __nv_bfloat16 l0 = __float2bfloat16(r0), l1 = __float2bfloat16(r1);
    hi = (uint32_t)__bfloat16_as_ushort(h0) | ((uint32_t)__bfloat16_as_ushort(h1) << 16);
    lo = (uint32_t)__bfloat16_as_ushort(l0) | ((uint32_t)__bfloat16_as_ushort(l1) << 16);
}
__device__ __forceinline__ float gate_fn(float h) {
    h = fminf(fmaxf(h, -30.f), 30.f);
    float e1 = __expf(-h);
    float e2 = e1 * e1;
    return ((1.f - e2) / (1.f + e2)) * (1.f / (1.f + e1));
}

// ---------------- pre-pass kernels ----------------
__global__ void transpose_x(const float* __restrict__ x, float* __restrict__ xt) {
    __shared__ float tile[32][33];
    int b = blockIdx.z, c0 = blockIdx.y * 32, t0 = blockIdx.x * 32;
    int lx = threadIdx.x, ly = threadIdx.y;
    #pragma unroll
    for (int i = 0; i < 32; i += 8)
        tile[ly + i][lx] = x[((size_t)b * CRES + c0 + ly + i) * T_LEN + t0 + lx];
    __syncthreads();
    #pragma unroll
    for (int i = 0; i < 32; i += 8)
        xt[((size_t)b * T_LEN + t0 + ly + i) * CRES + c0 + lx] = tile[lx][ly + i];
}

__global__ void prep_weights(const float* __restrict__ wd, const float* __restrict__ wr,
                             const float* __restrict__ wsk, __nv_bfloat16* __restrict__ img) {
    int blk = blockIdx.x, m = blockIdx.y;
    for (int e = threadIdx.x; e < 16384; e += 256) {
        int o = e >> 7, k = e & 127;
        float v;
        if      (m == 0) v = wd[((size_t)blk * 16384 + o * 128 + k) * 2 + 0];
        else if (m == 1) v = wd[((size_t)blk * 16384 + o * 128 + k) * 2 + 1];
        else if (m == 2) v = wr[(size_t)blk * 16384 + o * 128 + k];
        else if (m == 3) v = wsk[(size_t)blk * 32768 + o * 128 + k];
        else             v = wsk[(size_t)blk * 32768 + (o + 128) * 128 + k];
        __nv_bfloat16 hi = __float2bfloat16(v);
        float rem = v - __bfloat162float(hi);
        __nv_bfloat16 lo = __float2bfloat16(rem);
        size_t base = ((size_t)blk * 10 + (size_t)m * 2) * 16384;
        img[base + e] = hi;
        img[base + 16384 + e] = lo;
    }
}

// ---------------- main block kernel ----------------
__global__ void __launch_bounds__(THREADS, 1)
wnet_mma(const float* __restrict__ in, float* __restrict__ resout,
         const __nv_bfloat16* __restrict__ img, float* __restrict__ skipout, int dil)
{
    extern __shared__ char smem[];
    const uint32_t sb = smem_u32(smem);
    const int tid = threadIdx.x;
    const int lane = tid & 31, wid = tid >> 5;
    const int wm = wid & 3;        // M group (32 t rows)
    const int wn = wid >> 2;       // N group (32 out cols)
    const int b = blockIdx.y, t0 = blockIdx.x * 128;

    // per-lane ldmatrix address offsets (bytes)
    const uint32_t a_off = (uint32_t)(lane & 15) * PADB + (uint32_t)(lane >> 4) * 16;
    const uint32_t b_off = (uint32_t)((lane & 7) + ((lane >> 4) << 3)) * PADB
                         + (uint32_t)((lane >> 3) & 1) * 16;

    const float* src = in + (size_t)b * T_LEN * CRES;

    // ---- async weight pair loader (hi+lo images -> padded SMEM) ----
    auto load_w_async = [&](int imgidx) {
        const char* ghi = (const char*)(img + (size_t)imgidx * 16384);
        const char* glo = (const char*)(img + (size_t)(imgidx + 1) * 16384);
        #pragma unroll
        for (int i = 0; i < 4; ++i) {
            int e = tid + i * THREADS;
            uint32_t off = (uint32_t)(e >> 4) * PADB + (uint32_t)(e & 15) * 16;
            cpa16(sb + SM_WHI + off, ghi + (size_t)e * 16);
            cpa16(sb + SM_WLO + off, glo + (size_t)e * 16);
        }
        CP_COMMIT();
    };

    // ---- activation tile load + bf16 split (each thread: 1/4 row = 32 ch) ----
    auto load_split = [&](int smhi, int smlo, bool shifted) {
        int row = tid >> 2, q = tid & 3;
        int ts = shifted ? (t0 + row - dil) : (t0 + row);
        bool valid = ts >= 0;
        const float* rp = src + (size_t)(valid ? ts : 0) * CRES + q * 32;
        char* dh = smem + smhi + row * PADB + q * 64;
        char* dl = smem + smlo + row * PADB + q * 64;
        #pragma unroll
        for (int j = 0; j < 8; ++j) {
            float4 v = valid ? *(const float4*)(rp + j * 4) : make_float4(0.f, 0.f, 0.f, 0.f);
            uint32_t h0, l0, h1, l1;
            split2(v.x, v.y, h0, l0);
            split2(v.z, v.w, h1, l1);
            *(uint32_t*)(dh + j * 8)     = h0;
            *(uint32_t*)(dh + j * 8 + 4) = h1;
            *(uint32_t*)(dl + j * 8)     = l0;
            *(uint32_t*)(dl + j * 8 + 4) = l1;
        }
    };

    float acc[2][4][4];
    auto zero_acc = [&]() {
        #pragma unroll
        for (int mt = 0; mt < 2; ++mt)
            #pragma unroll
            for (int nt = 0; nt < 4; ++nt)
                #pragma unroll
                for (int j = 0; j < 4; ++j) acc[mt][nt][j] = 0.f;
    };

    // ---- fused 3-term split GEMM: acc += Ahi*Whi + Ahi*Wlo + Alo*Whi ----
    auto gemm3 = [&](uint32_t aHi, uint32_t aLo) {
        uint32_t AHi = sb + aHi + (uint32_t)wm * 32 * PADB + a_off;
        uint32_t ALo = sb + aLo + (uint32_t)wm * 32 * PADB + a_off;
        uint32_t BHi = sb + SM_WHI + (uint32_t)wn * 32 * PADB + b_off;
        uint32_t BLo = sb + SM_WLO + (uint32_t)wn * 32 * PADB + b_off;
        #pragma unroll
        for (int k0 = 0; k0 < 8; ++k0) {
            uint32_t ah[2][4], al[2][4], bh[2][4], bl[2][4];
            ldsm4(ah[0], AHi + k0 * 32);
            ldsm4(ah[1], AHi + 16 * PADB + k0 * 32);
            ldsm4(al[0], ALo + k0 * 32);
            ldsm4(al[1], ALo + 16 * PADB + k0 * 32);
            ldsm4(bh[0], BHi + k0 * 32);
            ldsm4(bh[1], BHi + 16 * PADB + k0 * 32);
            ldsm4(bl[0], BLo + k0 * 32);
            ldsm4(bl[1], BLo + 16 * PADB + k0 * 32);
            #pragma unroll
            for (int mt = 0; mt < 2; ++mt)
                #pragma unroll
                for (int nt = 0; nt < 4; ++nt) {
                    const uint32_t* bhp = &bh[nt >> 1][(nt & 1) * 2];
                    const uint32_t* blp = &bl[nt >> 1][(nt & 1) * 2];
                    mma16816(acc[mt][nt], ah[mt], bhp);
                    mma16816(acc[mt][nt], ah[mt], blp);
                    mma16816(acc[mt][nt], al[mt], bhp);
                }
        }
    };

    // ================= phase 1: h = Wd0 @ Xd + Wd1 @ Xc =================
    load_w_async(0);                             // wd0 hi/lo
    load_split(SM_XCHI, SM_XCLO, false);
    load_split(SM_XDHI, SM_XDLO, true);
    CP_WAIT0();
    __syncthreads();

    zero_acc();
    gemm3(SM_XDHI, SM_XDLO);
    __syncthreads();                             // done reading W(wd0)
    load_w_async(2);                             // wd1 hi/lo
    CP_WAIT0();
    __syncthreads();
    gemm3(SM_XCHI, SM_XCLO);
    __syncthreads();                             // done reading XD & W

    // ---- gate in registers -> G (bf16 split) into XD slots; prefetch wres ----
    load_w_async(4);
    #pragma unroll
    for (int mt = 0; mt < 2; ++mt)
        #pragma unroll
        for (int nt = 0; nt < 4; ++nt) {
            int r0 = wm * 32 + mt * 16 + (lane >> 2);
            int c  = wn * 32 + nt * 8 + (lane & 3) * 2;
            #pragma unroll
            for (int h = 0; h < 2; ++h) {
                float g0 = gate_fn(acc[mt][nt][h * 2 + 0]);
                float g1 = gate_fn(acc[mt][nt][h * 2 + 1]);
                uint32_t hi, lo;
                split2(g0, g1, hi, lo);
                int r = r0 + h * 8;
                *(uint32_t*)(smem + SM_XDHI + r * PADB + c * 2) = hi;
                *(uint32_t*)(smem + SM_XDLO + r * PADB + c * 2) = lo;
            }
        }
    CP_WAIT0();
    __syncthreads();

    // ================= phase 2: res = Wres @ G; out = res + Xc =================
    zero_acc();
    gemm3(SM_XDHI, SM_XDLO);
    {
        float* dst = resout + ((size_t)b * T_LEN + t0) * CRES;
        const float* xc = src + (size_t)t0 * CRES;
        #pragma unroll
        for (int mt = 0; mt < 2; ++mt)
            #pragma unroll
            for (int nt = 0; nt < 4; ++nt) {
                int c = wn * 32 + nt * 8 + (lane & 3) * 2;
                #pragma unroll
                for (int h = 0; h < 2; ++h) {
                    int r = wm * 32 + mt * 16 + (lane >> 2) + h * 8;
                    float2 x = *(const float2*)(xc + (size_t)r * CRES + c);
                    float2 o;
                    o.x = acc[mt][nt][h * 2 + 0] + x.x;
                    o.y = acc[mt][nt][h * 2 + 1] + x.y;
                    *(float2*)(dst + (size_t)r * CRES + c) = o;
                }
            }
    }
    __syncthreads();                             // done reading W(wres) before overwrite

    // ================= phase 3: skip = Wskip @ G (last 4096 t only) =================
    if (t0 >= SKIPSTART) {
        float* bn = (float*)(smem + SM_BOUNCE);
        float* sbase = skipout + (size_t)b * 256 * SKIPLEN + (t0 - SKIPSTART);
        #pragma unroll 1
        for (int half = 0; half < 2; ++half) {
            load_w_async(6 + half * 2);
            CP_WAIT0();
            __syncthreads();
            zero_acc();
            gemm3(SM_XDHI, SM_XDLO);
            // stage acc -> bounce [t][o], stride BSTR floats
            #pragma unroll
            for (int mt = 0; mt < 2; ++mt)
                #pragma unroll
                for (int nt = 0; nt < 4; ++nt) {
                    int c = wn * 32 + nt * 8 + (lane & 3) * 2;
                    #pragma unroll
                    for (int h = 0; h < 2; ++h) {
                        int r = wm * 32 + mt * 16 + (lane >> 2) + h * 8;
                        bn[r * BSTR + c]     = acc[mt][nt][h * 2 + 0];
                        bn[r * BSTR + c + 1] = acc[mt][nt][h * 2 + 1];
                    }
                }
            __syncthreads();
            // coalesced write: 16 warps x 4 o-rows per iter, 2 iters
            #pragma unroll 1
            for (int it = 0; it < 2; ++it) {
                int o = it * 64 + wid * 4 + (lane >> 3);
                float* gdst = sbase + (size_t)(half * 128 + o) * SKIPLEN;
                #pragma unroll
                for (int j = 0; j < 4; ++j) {
                    int tt = (lane & 7) * 4 + j * 32;
                    float4 v;
                    v.x = bn[(tt + 0) * BSTR + o];
                    v.y = bn[(tt + 1) * BSTR + o];
                    v.z = bn[(tt + 2) * BSTR + o];
                    v.w = bn[(tt + 3) * BSTR + o];
                    *(float4*)(gdst + tt) = v;
                }
            }
            __syncthreads();
        }
    }
}

// ---------------- host ----------------
extern "C" void kernel_launch(void* const* d_in, const int* in_sizes, int n_in,
                              void* d_out, int out_size)
{
    const float* x      = (const float*)d_in[0];
    const float* w_dil  = (const float*)d_in[1];
    const float* w_res  = (const float*)d_in[2];
    const float* w_skip = (const float*)d_in[3];
    float* out = (float*)d_out;

    float *pA, *pB;
    __nv_bfloat16* pimg;
    cudaGetSymbolAddress((void**)&pA, g_actA);
    cudaGetSymbolAddress((void**)&pB, g_actB);
    cudaGetSymbolAddress((void**)&pimg, g_wimg);

    cudaFuncSetAttribute(wnet_mma, cudaFuncAttributeMaxDynamicSharedMemorySize, SM_TOTAL);

    transpose_x<<<dim3(T_LEN / 32, CRES / 32, BATCH), dim3(32, 8)>>>(x, pA);
    prep_weights<<<dim3(NBLK, 5), 256>>>(w_dil, w_res, w_skip, pimg);

    for (int i = 0; i < NBLK; ++i) {
        const float* srcp = (i & 1) ? pB : pA;
        float* dstp       = (i & 1) ? pA : pB;
        wnet_mma<<<dim3(T_LEN / 128, BATCH), THREADS, SM_TOTAL>>>(
            srcp, dstp,
            pimg + (size_t)i * 10 * 16384,
            out + (size_t)i * BATCH * 256 * SKIPLEN,
            1 << (i % 10));
    }
}

// round 5
// speedup vs baseline: 2.5559x; 1.1826x over previous
#include <cuda_runtime.h>
#include <cuda_bf16.h>
#include <cstdint>

#define T_LEN 16384
#define BATCH 4
#define CRES 128
#define NBLK 40
#define SKIPLEN 4096
#define SKIPSTART (T_LEN - SKIPLEN)

#define THREADS 256
#define TT 64

// SMEM layout (bytes) — XOR-swizzled, zero padding
#define SM_AHI 0            // 64 rows x 256B
#define SM_ALO 16384
#define SM_WHI 32768        // 128 rows x 256B
#define SM_WLO 65536
#define SM_TOTAL 98304
#define SM_BOUNCE SM_WHI    // fp32 bounce (skip phase only; W areas dead then)
#define BSTR 129

// ---------------- device scratch ----------------
__device__ float g_actA[(size_t)BATCH * T_LEN * CRES];
__device__ float g_actB[(size_t)BATCH * T_LEN * CRES];
// per block: 10 images of 128x128 bf16 row-major [o][k]:
// [0]=wd0hi [1]=wd0lo [2]=wd1hi [3]=wd1lo [4]=wreshi [5]=wreslo
// [6]=wskAhi [7]=wskAlo [8]=wskBhi [9]=wskBlo
__device__ __align__(16) __nv_bfloat16 g_wimg[(size_t)NBLK * 10 * 16384];

// ---------------- helpers ----------------
__device__ __forceinline__ uint32_t smem_u32(const void* p) {
    uint32_t a;
    asm("{ .reg .u64 t; cvta.to.shared.u64 t, %1; cvt.u32.u64 %0, t; }" : "=r"(a) : "l"(p));
    return a;
}
__device__ __forceinline__ void ldsm4(uint32_t* r, uint32_t addr) {
    asm volatile("ldmatrix.sync.aligned.m8n8.x4.shared.b16 {%0,%1,%2,%3}, [%4];"
                 : "=r"(r[0]), "=r"(r[1]), "=r"(r[2]), "=r"(r[3]) : "r"(addr));
}
__device__ __forceinline__ void mma16816(float* d, const uint32_t* a, const uint32_t* b) {
    asm volatile("mma.sync.aligned.m16n8k16.row.col.f32.bf16.bf16.f32 "
                 "{%0,%1,%2,%3},{%4,%5,%6,%7},{%8,%9},{%0,%1,%2,%3};"
                 : "+f"(d[0]), "+f"(d[1]), "+f"(d[2]), "+f"(d[3])
                 : "r"(a[0]), "r"(a[1]), "r"(a[2]), "r"(a[3]), "r"(b[0]), "r"(b[1]));
}
__device__ __forceinline__ void cpa16(uint32_t dst, const void* src) {
    asm volatile("cp.async.cg.shared.global [%0], [%1], 16;" :: "r"(dst), "l"(src));
}
#define CP_COMMIT() asm volatile("cp.async.commit_group;" ::: "memory")
#define CP_WAIT0()  asm volatile("cp.async.wait_group 0;" ::: "memory")

__device__ __forceinline__ void split2(float x0, float x1, uint32_t& hi, uint32_t& lo) {
    __nv_bfloat16 h0 = __float2bfloat16(x0), h1 = __float2bfloat16(x1);
    float r0 = x0 - __bfloat162float(h0), r1 = x1 - __bfloat162float(h1);
    __nv_bfloat16 l0 = __float2bfloat16(r0), l1 = __float2bfloat16(r1);
    hi = (uint32_t)__bfloat16_as_ushort(h0) | ((uint32_t)__bfloat16_as_ushort(h1) << 16);
    lo = (uint32_t)__bfloat16_as_ushort(l0) | ((uint32_t)__bfloat16_as_ushort(l1) << 16);
}
__device__ __forceinline__ float gate_fn(float h) {
    h = fminf(fmaxf(h, -30.f), 30.f);
    float e1 = __expf(-h);
    float e2 = e1 * e1;
    return ((1.f - e2) / (1.f + e2)) * (1.f / (1.f + e1));
}

// ---------------- pre-pass kernels ----------------
__global__ void transpose_x(const float* __restrict__ x, float* __restrict__ xt) {
    __shared__ float tile[32][33];
    int b = blockIdx.z, c0 = blockIdx.y * 32, t0 = blockIdx.x * 32;
    int lx = threadIdx.x, ly = threadIdx.y;
    #pragma unroll
    for (int i = 0; i < 32; i += 8)
        tile[ly + i][lx] = x[((size_t)b * CRES + c0 + ly + i) * T_LEN + t0 + lx];
    __syncthreads();
    #pragma unroll
    for (int i = 0; i < 32; i += 8)
        xt[((size_t)b * T_LEN + t0 + ly + i) * CRES + c0 + lx] = tile[lx][ly + i];
}

__global__ void prep_weights(const float* __restrict__ wd, const float* __restrict__ wr,
                             const float* __restrict__ wsk, __nv_bfloat16* __restrict__ img) {
    int blk = blockIdx.x, m = blockIdx.y;
    for (int e = threadIdx.x; e < 16384; e += 256) {
        int o = e >> 7, k = e & 127;
        float v;
        if      (m == 0) v = wd[((size_t)blk * 16384 + o * 128 + k) * 2 + 0];
        else if (m == 1) v = wd[((size_t)blk * 16384 + o * 128 + k) * 2 + 1];
        else if (m == 2) v = wr[(size_t)blk * 16384 + o * 128 + k];
        else if (m == 3) v = wsk[(size_t)blk * 32768 + o * 128 + k];
        else             v = wsk[(size_t)blk * 32768 + (o + 128) * 128 + k];
        __nv_bfloat16 hi = __float2bfloat16(v);
        float rem = v - __bfloat162float(hi);
        __nv_bfloat16 lo = __float2bfloat16(rem);
        size_t base = ((size_t)blk * 10 + (size_t)m * 2) * 16384;
        img[base + e] = hi;
        img[base + 16384 + e] = lo;
    }
}

// ---------------- main block kernel ----------------
__global__ void __launch_bounds__(THREADS, 2)
wnet_mma(const float* __restrict__ in, float* __restrict__ resout,
         const __nv_bfloat16* __restrict__ img, float* __restrict__ skipout, int dil)
{
    extern __shared__ char smem[];
    const uint32_t sb = smem_u32(smem);
    const int tid = threadIdx.x;
    const int lane = tid & 31, wid = tid >> 5;
    const int wm = wid & 1;        // 2 M groups (32 t rows each)
    const int wn = wid >> 1;       // 4 N groups (32 out cols each)
    const int b = blockIdx.y, t0 = blockIdx.x * TT;

    // per-lane ldmatrix constants (swizzled)
    const uint32_t arow = (uint32_t)(wm * 32 + (lane & 15)) * 256;
    const uint32_t rxa  = (uint32_t)(lane & 7) << 4;
    const uint32_t kla  = (uint32_t)(lane >> 4) << 4;
    const uint32_t brow = (uint32_t)(wn * 32 + (lane & 7) + ((lane >> 4) << 3)) * 256;
    const uint32_t rxb  = (uint32_t)(lane & 7) << 4;
    const uint32_t klb  = (uint32_t)((lane >> 3) & 1) << 4;

    const float* src = in + (size_t)b * T_LEN * CRES;

    // ---- async weight pair loader (row-major image -> swizzled SMEM) ----
    auto load_w_async = [&](int imgidx) {
        const char* ghi = (const char*)(img + (size_t)imgidx * 16384);
        const char* glo = ghi + 32768;
        #pragma unroll
        for (int i = 0; i < 8; ++i) {
            uint32_t e = (uint32_t)tid + i * THREADS;       // 0..2047 16B chunks
            uint32_t row = e >> 4, k = e & 15;
            uint32_t off = row * 256 + ((k ^ (row & 7)) << 4);
            cpa16(sb + SM_WHI + off, ghi + (size_t)e * 16);
            cpa16(sb + SM_WLO + off, glo + (size_t)e * 16);
        }
        CP_COMMIT();
    };

    // ---- activation tile load + bf16 split into A slots ----
    auto load_split = [&](bool shifted) {
        int row = tid >> 2, q = tid & 3;
        int ts = shifted ? (t0 + row - dil) : (t0 + row);
        bool valid = ts >= 0;
        const float* rp = src + (size_t)(valid ? ts : 0) * CRES + q * 32;
        uint32_t rbase = (uint32_t)row * 256;
        uint32_t rw = (uint32_t)(row & 7);
        #pragma unroll
        for (int j = 0; j < 8; ++j) {
            float4 v = valid ? *(const float4*)(rp + j * 4) : make_float4(0.f, 0.f, 0.f, 0.f);
            uint32_t h0, l0, h1, l1;
            split2(v.x, v.y, h0, l0);
            split2(v.z, v.w, h1, l1);
            uint32_t chunk = (uint32_t)q * 4 + (j >> 1);
            uint32_t off = rbase + ((chunk ^ rw) << 4) + (j & 1) * 8;
            *(uint32_t*)(smem + SM_AHI + off)     = h0;
            *(uint32_t*)(smem + SM_AHI + off + 4) = h1;
            *(uint32_t*)(smem + SM_ALO + off)     = l0;
            *(uint32_t*)(smem + SM_ALO + off + 4) = l1;
        }
    };

    float acc[2][4][4];
    auto zero_acc = [&]() {
        #pragma unroll
        for (int mt = 0; mt < 2; ++mt)
            #pragma unroll
            for (int nt = 0; nt < 4; ++nt)
                #pragma unroll
                for (int j = 0; j < 4; ++j) acc[mt][nt][j] = 0.f;
    };

    // ---- fused 3-term split GEMM: acc += Ahi*Whi + Ahi*Wlo + Alo*Whi ----
    auto gemm3 = [&]() {
        #pragma unroll
        for (int k0 = 0; k0 < 8; ++k0) {
            uint32_t aoffs = (((uint32_t)k0 * 32 + kla) ^ rxa);
            uint32_t boffs = (((uint32_t)k0 * 32 + klb) ^ rxb);
            uint32_t ah[2][4], al[2][4], bh[2][4], bl[2][4];
            ldsm4(ah[0], sb + SM_AHI + arow + aoffs);
            ldsm4(ah[1], sb + SM_AHI + arow + 4096 + aoffs);
            ldsm4(al[0], sb + SM_ALO + arow + aoffs);
            ldsm4(al[1], sb + SM_ALO + arow + 4096 + aoffs);
            ldsm4(bh[0], sb + SM_WHI + brow + boffs);
            ldsm4(bh[1], sb + SM_WHI + brow + 4096 + boffs);
            ldsm4(bl[0], sb + SM_WLO + brow + boffs);
            ldsm4(bl[1], sb + SM_WLO + brow + 4096 + boffs);
            #pragma unroll
            for (int mt = 0; mt < 2; ++mt)
                #pragma unroll
                for (int nt = 0; nt < 4; ++nt) {
                    const uint32_t* bhp = &bh[nt >> 1][(nt & 1) * 2];
                    const uint32_t* blp = &bl[nt >> 1][(nt & 1) * 2];
                    mma16816(acc[mt][nt], ah[mt], bhp);
                    mma16816(acc[mt][nt], ah[mt], blp);
                    mma16816(acc[mt][nt], al[mt], bhp);
                }
        }
    };

    // ================= phase 1a: h += Wd0 @ Xd =================
    load_w_async(0);
    load_split(true);                           // Xd (shifted)
    CP_WAIT0();
    __syncthreads();
    zero_acc();
    gemm3();
    __syncthreads();                            // done reading A(Xd), W(wd0)

    // ================= phase 1b: h += Wd1 @ Xc =================
    load_w_async(2);
    load_split(false);                          // Xc overwrites A slots
    CP_WAIT0();
    __syncthreads();
    gemm3();
    __syncthreads();                            // done reading A(Xc), W(wd1)

    // ---- gate -> G into A slots; prefetch wres ----
    load_w_async(4);
    #pragma unroll
    for (int mt = 0; mt < 2; ++mt)
        #pragma unroll
        for (int nt = 0; nt < 4; ++nt) {
            int c = wn * 32 + nt * 8 + (lane & 3) * 2;
            #pragma unroll
            for (int h = 0; h < 2; ++h) {
                int r = wm * 32 + mt * 16 + (lane >> 2) + h * 8;
                float g0 = gate_fn(acc[mt][nt][h * 2 + 0]);
                float g1 = gate_fn(acc[mt][nt][h * 2 + 1]);
                uint32_t hi, lo;
                split2(g0, g1, hi, lo);
                uint32_t off = (uint32_t)r * 256
                             + (uint32_t)((((c >> 3) ^ (r & 7)) << 4) + (c & 7) * 2);
                *(uint32_t*)(smem + SM_AHI + off) = hi;
                *(uint32_t*)(smem + SM_ALO + off) = lo;
            }
        }
    CP_WAIT0();
    __syncthreads();

    // ================= phase 2: res = Wres @ G; out = res + Xc(global) =================
    zero_acc();
    gemm3();
    {
        float* dst = resout + ((size_t)b * T_LEN + t0) * CRES;
        const float* xc = src + (size_t)t0 * CRES;
        #pragma unroll
        for (int mt = 0; mt < 2; ++mt)
            #pragma unroll
            for (int nt = 0; nt < 4; ++nt) {
                int c = wn * 32 + nt * 8 + (lane & 3) * 2;
                #pragma unroll
                for (int h = 0; h < 2; ++h) {
                    int r = wm * 32 + mt * 16 + (lane >> 2) + h * 8;
                    float2 x = *(const float2*)(xc + (size_t)r * CRES + c);
                    float2 o;
                    o.x = acc[mt][nt][h * 2 + 0] + x.x;
                    o.y = acc[mt][nt][h * 2 + 1] + x.y;
                    *(float2*)(dst + (size_t)r * CRES + c) = o;
                }
            }
    }
    __syncthreads();                            // all done reading W(wres)

    // ================= phase 3: skip = Wskip @ G (last 4096 t only) =================
    if (t0 >= SKIPSTART) {
        float* bn = (float*)(smem + SM_BOUNCE);
        float* sbase = skipout + (size_t)b * 256 * SKIPLEN + (t0 - SKIPSTART);
        #pragma unroll 1
        for (int half = 0; half < 2; ++half) {
            load_w_async(6 + half * 2);
            CP_WAIT0();
            __syncthreads();
            zero_acc();
            gemm3();
            __syncthreads();                    // all warps done reading W before bounce
            #pragma unroll
            for (int mt = 0; mt < 2; ++mt)
                #pragma unroll
                for (int nt = 0; nt < 4; ++nt) {
                    int c = wn * 32 + nt * 8 + (lane & 3) * 2;
                    #pragma unroll
                    for (int h = 0; h < 2; ++h) {
                        int r = wm * 32 + mt * 16 + (lane >> 2) + h * 8;
                        bn[r * BSTR + c]     = acc[mt][nt][h * 2 + 0];
                        bn[r * BSTR + c + 1] = acc[mt][nt][h * 2 + 1];
                    }
                }
            __syncthreads();
            // coalesced write: 8 warps x 16 o-rows each, 64 t per row
            #pragma unroll 1
            for (int it = 0; it < 16; ++it) {
                int o = it * 8 + wid;
                float* gdst = sbase + (size_t)(half * 128 + o) * SKIPLEN;
                float2 v;
                v.x = bn[(lane * 2 + 0) * BSTR + o];
                v.y = bn[(lane * 2 + 1) * BSTR + o];
                *(float2*)(gdst + lane * 2) = v;
            }
            __syncthreads();
        }
    }
}

// ---------------- host ----------------
extern "C" void kernel_launch(void* const* d_in, const int* in_sizes, int n_in,
                              void* d_out, int out_size)
{
    const float* x      = (const float*)d_in[0];
    const float* w_dil  = (const float*)d_in[1];
    const float* w_res  = (const float*)d_in[2];
    const float* w_skip = (const float*)d_in[3];
    float* out = (float*)d_out;

    float *pA, *pB;
    __nv_bfloat16* pimg;
    cudaGetSymbolAddress((void**)&pA, g_actA);
    cudaGetSymbolAddress((void**)&pB, g_actB);
    cudaGetSymbolAddress((void**)&pimg, g_wimg);

    cudaFuncSetAttribute(wnet_mma, cudaFuncAttributeMaxDynamicSharedMemorySize, SM_TOTAL);

    transpose_x<<<dim3(T_LEN / 32, CRES / 32, BATCH), dim3(32, 8)>>>(x, pA);
    prep_weights<<<dim3(NBLK, 5), 256>>>(w_dil, w_res, w_skip, pimg);

    for (int i = 0; i < NBLK; ++i) {
        const float* srcp = (i & 1) ? pB : pA;
        float* dstp       = (i & 1) ? pA : pB;
        wnet_mma<<<dim3(T_LEN / TT, BATCH), THREADS, SM_TOTAL>>>(
            srcp, dstp,
            pimg + (size_t)i * 10 * 16384,
            out + (size_t)i * BATCH * 256 * SKIPLEN,
            1 << (i % 10));
    }
}

// round 6
// speedup vs baseline: 3.2956x; 1.2894x over previous
#include <cuda_runtime.h>
#include <cuda_fp16.h>
#include <cstdint>

#define T_LEN 16384
#define BATCH 4
#define CRES 128
#define NBLK 40
#define SKIPLEN 4096
#define SKIPSTART (T_LEN - SKIPLEN)

#define THREADS 256
#define TT 64

// SMEM layout (bytes) — XOR-swizzled, zero padding
#define SM_XD  0            // 64 rows x 256B fp16 (Xd, later G)
#define SM_XC  16384        // 64 rows x 256B fp16 (Xc)
#define SM_WHI 32768        // 128 rows x 256B
#define SM_WLO 65536
#define SM_TOTAL 98304
#define SM_BOUNCE SM_WHI    // fp32 bounce (skip phase only; W areas dead then)
#define BSTR 129

// ---------------- device scratch ----------------
__device__ float g_actA[(size_t)BATCH * T_LEN * CRES];
__device__ float g_actB[(size_t)BATCH * T_LEN * CRES];
// per block: 10 images of 128x128 fp16 row-major [o][k]:
// [0]=wd0hi [1]=wd0lo [2]=wd1hi [3]=wd1lo [4]=wreshi [5]=wreslo
// [6]=wskAhi [7]=wskAlo [8]=wskBhi [9]=wskBlo
__device__ __align__(16) __half g_wimg[(size_t)NBLK * 10 * 16384];

// ---------------- helpers ----------------
__device__ __forceinline__ uint32_t smem_u32(const void* p) {
    uint32_t a;
    asm("{ .reg .u64 t; cvta.to.shared.u64 t, %1; cvt.u32.u64 %0, t; }" : "=r"(a) : "l"(p));
    return a;
}
__device__ __forceinline__ void ldsm4(uint32_t* r, uint32_t addr) {
    asm volatile("ldmatrix.sync.aligned.m8n8.x4.shared.b16 {%0,%1,%2,%3}, [%4];"
                 : "=r"(r[0]), "=r"(r[1]), "=r"(r[2]), "=r"(r[3]) : "r"(addr));
}
__device__ __forceinline__ void mma16816(float* d, const uint32_t* a, const uint32_t* b) {
    asm volatile("mma.sync.aligned.m16n8k16.row.col.f32.f16.f16.f32 "
                 "{%0,%1,%2,%3},{%4,%5,%6,%7},{%8,%9},{%0,%1,%2,%3};"
                 : "+f"(d[0]), "+f"(d[1]), "+f"(d[2]), "+f"(d[3])
                 : "r"(a[0]), "r"(a[1]), "r"(a[2]), "r"(a[3]), "r"(b[0]), "r"(b[1]));
}
__device__ __forceinline__ void cpa16(uint32_t dst, const void* src) {
    asm volatile("cp.async.cg.shared.global [%0], [%1], 16;" :: "r"(dst), "l"(src));
}
#define CP_COMMIT() asm volatile("cp.async.commit_group;" ::: "memory")
#define CP_WAIT0()  asm volatile("cp.async.wait_group 0;" ::: "memory")

__device__ __forceinline__ uint32_t pack_h2(float x0, float x1) {
    __half2 h = __floats2half2_rn(x0, x1);
    return *reinterpret_cast<uint32_t*>(&h);
}
__device__ __forceinline__ float gate_fn(float h) {
    h = fminf(fmaxf(h, -30.f), 30.f);
    float e1 = __expf(-h);
    float e2 = e1 * e1;
    return ((1.f - e2) / (1.f + e2)) * (1.f / (1.f + e1));
}

// ---------------- pre-pass kernels ----------------
__global__ void transpose_x(const float* __restrict__ x, float* __restrict__ xt) {
    __shared__ float tile[32][33];
    int b = blockIdx.z, c0 = blockIdx.y * 32, t0 = blockIdx.x * 32;
    int lx = threadIdx.x, ly = threadIdx.y;
    #pragma unroll
    for (int i = 0; i < 32; i += 8)
        tile[ly + i][lx] = x[((size_t)b * CRES + c0 + ly + i) * T_LEN + t0 + lx];
    __syncthreads();
    #pragma unroll
    for (int i = 0; i < 32; i += 8)
        xt[((size_t)b * T_LEN + t0 + ly + i) * CRES + c0 + lx] = tile[lx][ly + i];
}

__global__ void prep_weights(const float* __restrict__ wd, const float* __restrict__ wr,
                             const float* __restrict__ wsk, __half* __restrict__ img) {
    int blk = blockIdx.x, m = blockIdx.y;
    for (int e = threadIdx.x; e < 16384; e += 256) {
        int o = e >> 7, k = e & 127;
        float v;
        if      (m == 0) v = wd[((size_t)blk * 16384 + o * 128 + k) * 2 + 0];
        else if (m == 1) v = wd[((size_t)blk * 16384 + o * 128 + k) * 2 + 1];
        else if (m == 2) v = wr[(size_t)blk * 16384 + o * 128 + k];
        else if (m == 3) v = wsk[(size_t)blk * 32768 + o * 128 + k];
        else             v = wsk[(size_t)blk * 32768 + (o + 128) * 128 + k];
        __half hi = __float2half_rn(v);
        __half lo = __float2half_rn(v - __half2float(hi));
        size_t base = ((size_t)blk * 10 + (size_t)m * 2) * 16384;
        img[base + e] = hi;
        img[base + 16384 + e] = lo;
    }
}

// ---------------- main block kernel ----------------
__global__ void __launch_bounds__(THREADS, 2)
wnet_mma(const float* __restrict__ in, float* __restrict__ resout,
         const __half* __restrict__ img, float* __restrict__ skipout, int dil)
{
    extern __shared__ char smem[];
    const uint32_t sb = smem_u32(smem);
    const int tid = threadIdx.x;
    const int lane = tid & 31, wid = tid >> 5;
    const int wm = wid & 1;        // 2 M groups (32 t rows each)
    const int wn = wid >> 1;       // 4 N groups (32 out cols each)
    const int b = blockIdx.y, t0 = blockIdx.x * TT;

    // per-lane ldmatrix constants (swizzled, 256B rows / 16 chunks)
    const uint32_t arow = (uint32_t)(wm * 32 + (lane & 15)) * 256;
    const uint32_t rxa  = (uint32_t)(lane & 7) << 4;
    const uint32_t kla  = (uint32_t)(lane >> 4) << 4;
    const uint32_t brow = (uint32_t)(wn * 32 + (lane & 7) + ((lane >> 4) << 3)) * 256;
    const uint32_t rxb  = (uint32_t)(lane & 7) << 4;
    const uint32_t klb  = (uint32_t)((lane >> 3) & 1) << 4;

    const float* src = in + (size_t)b * T_LEN * CRES;

    // ---- async weight pair loader (row-major image -> swizzled SMEM) ----
    auto load_w_async = [&](int imgidx) {
        const char* ghi = (const char*)(img + (size_t)imgidx * 16384);
        const char* glo = ghi + 32768;
        #pragma unroll
        for (int i = 0; i < 8; ++i) {
            uint32_t e = (uint32_t)tid + i * THREADS;       // 0..2047 16B chunks
            uint32_t row = e >> 4, k = e & 15;
            uint32_t off = row * 256 + ((k ^ (row & 7)) << 4);
            cpa16(sb + SM_WHI + off, ghi + (size_t)e * 16);
            cpa16(sb + SM_WLO + off, glo + (size_t)e * 16);
        }
        CP_COMMIT();
    };

    // ---- activation tile load -> single fp16 slot ----
    auto load_half = [&](int slot, bool shifted) {
        int row = tid >> 2, q = tid & 3;
        int ts = shifted ? (t0 + row - dil) : (t0 + row);
        bool valid = ts >= 0;
        const float* rp = src + (size_t)(valid ? ts : 0) * CRES + q * 32;
        uint32_t rbase = (uint32_t)row * 256;
        uint32_t rw = (uint32_t)(row & 7);
        #pragma unroll
        for (int j = 0; j < 8; ++j) {
            float4 v = valid ? *(const float4*)(rp + j * 4) : make_float4(0.f, 0.f, 0.f, 0.f);
            uint32_t chunk = (uint32_t)q * 4 + (j >> 1);
            uint32_t off = rbase + ((chunk ^ rw) << 4) + (j & 1) * 8;
            *(uint32_t*)(smem + slot + off)     = pack_h2(v.x, v.y);
            *(uint32_t*)(smem + slot + off + 4) = pack_h2(v.z, v.w);
        }
    };

    float acc[2][4][4];
    auto zero_acc = [&]() {
        #pragma unroll
        for (int mt = 0; mt < 2; ++mt)
            #pragma unroll
            for (int nt = 0; nt < 4; ++nt)
                #pragma unroll
                for (int j = 0; j < 4; ++j) acc[mt][nt][j] = 0.f;
    };

    // ---- fused 2-term split GEMM: acc += A*Whi + A*Wlo ----
    auto gemm2 = [&](uint32_t aSlot) {
        #pragma unroll
        for (int k0 = 0; k0 < 8; ++k0) {
            uint32_t aoffs = (((uint32_t)k0 * 32 + kla) ^ rxa);
            uint32_t boffs = (((uint32_t)k0 * 32 + klb) ^ rxb);
            uint32_t a[2][4], bh[2][4], bl[2][4];
            ldsm4(a[0], sb + aSlot + arow + aoffs);
            ldsm4(a[1], sb + aSlot + arow + 4096 + aoffs);
            ldsm4(bh[0], sb + SM_WHI + brow + boffs);
            ldsm4(bh[1], sb + SM_WHI + brow + 4096 + boffs);
            ldsm4(bl[0], sb + SM_WLO + brow + boffs);
            ldsm4(bl[1], sb + SM_WLO + brow + 4096 + boffs);
            #pragma unroll
            for (int mt = 0; mt < 2; ++mt)
                #pragma unroll
                for (int nt = 0; nt < 4; ++nt) {
                    mma16816(acc[mt][nt], a[mt], &bh[nt >> 1][(nt & 1) * 2]);
                    mma16816(acc[mt][nt], a[mt], &bl[nt >> 1][(nt & 1) * 2]);
                }
        }
    };

    // ================= phase 1: h = Wd0 @ Xd + Wd1 @ Xc =================
    load_w_async(0);
    load_half(SM_XD, true);                     // Xd (shifted)
    load_half(SM_XC, false);                    // Xc
    CP_WAIT0();
    __syncthreads();
    zero_acc();
    gemm2(SM_XD);
    __syncthreads();                            // W(wd0) consumed
    load_w_async(2);
    CP_WAIT0();
    __syncthreads();
    gemm2(SM_XC);
    __syncthreads();                            // W(wd1) consumed

    // ---- gate -> G into XD slot; prefetch wres ----
    load_w_async(4);
    #pragma unroll
    for (int mt = 0; mt < 2; ++mt)
        #pragma unroll
        for (int nt = 0; nt < 4; ++nt) {
            int c = wn * 32 + nt * 8 + (lane & 3) * 2;
            #pragma unroll
            for (int h = 0; h < 2; ++h) {
                int r = wm * 32 + mt * 16 + (lane >> 2) + h * 8;
                float g0 = gate_fn(acc[mt][nt][h * 2 + 0]);
                float g1 = gate_fn(acc[mt][nt][h * 2 + 1]);
                uint32_t off = (uint32_t)r * 256
                             + (uint32_t)((((c >> 3) ^ (r & 7)) << 4) + (c & 7) * 2);
                *(uint32_t*)(smem + SM_XD + off) = pack_h2(g0, g1);
            }
        }
    CP_WAIT0();
    __syncthreads();

    // ================= phase 2: res = Wres @ G; out = res + Xc(global) =================
    zero_acc();
    gemm2(SM_XD);
    {
        float* dst = resout + ((size_t)b * T_LEN + t0) * CRES;
        const float* xc = src + (size_t)t0 * CRES;
        #pragma unroll
        for (int mt = 0; mt < 2; ++mt)
            #pragma unroll
            for (int nt = 0; nt < 4; ++nt) {
                int c = wn * 32 + nt * 8 + (lane & 3) * 2;
                #pragma unroll
                for (int h = 0; h < 2; ++h) {
                    int r = wm * 32 + mt * 16 + (lane >> 2) + h * 8;
                    float2 x = *(const float2*)(xc + (size_t)r * CRES + c);
                    float2 o;
                    o.x = acc[mt][nt][h * 2 + 0] + x.x;
                    o.y = acc[mt][nt][h * 2 + 1] + x.y;
                    *(float2*)(dst + (size_t)r * CRES + c) = o;
                }
            }
    }
    __syncthreads();                            // W(wres) consumed

    // ================= phase 3: skip = Wskip @ G (last 4096 t only) =================
    if (t0 >= SKIPSTART) {
        float* bn = (float*)(smem + SM_BOUNCE);
        float* sbase = skipout + (size_t)b * 256 * SKIPLEN + (t0 - SKIPSTART);
        #pragma unroll 1
        for (int half = 0; half < 2; ++half) {
            load_w_async(6 + half * 2);
            CP_WAIT0();
            __syncthreads();
            zero_acc();
            gemm2(SM_XD);
            __syncthreads();                    // all warps done reading W before bounce
            #pragma unroll
            for (int mt = 0; mt < 2; ++mt)
                #pragma unroll
                for (int nt = 0; nt < 4; ++nt) {
                    int c = wn * 32 + nt * 8 + (lane & 3) * 2;
                    #pragma unroll
                    for (int h = 0; h < 2; ++h) {
                        int r = wm * 32 + mt * 16 + (lane >> 2) + h * 8;
                        bn[r * BSTR + c]     = acc[mt][nt][h * 2 + 0];
                        bn[r * BSTR + c + 1] = acc[mt][nt][h * 2 + 1];
                    }
                }
            __syncthreads();
            // coalesced write: 8 warps x 16 o-rows each, 64 t per row
            #pragma unroll 1
            for (int it = 0; it < 16; ++it) {
                int o = it * 8 + wid;
                float* gdst = sbase + (size_t)(half * 128 + o) * SKIPLEN;
                float2 v;
                v.x = bn[(lane * 2 + 0) * BSTR + o];
                v.y = bn[(lane * 2 + 1) * BSTR + o];
                *(float2*)(gdst + lane * 2) = v;
            }
            __syncthreads();
        }
    }
}

// ---------------- host ----------------
extern "C" void kernel_launch(void* const* d_in, const int* in_sizes, int n_in,
                              void* d_out, int out_size)
{
    const float* x      = (const float*)d_in[0];
    const float* w_dil  = (const float*)d_in[1];
    const float* w_res  = (const float*)d_in[2];
    const float* w_skip = (const float*)d_in[3];
    float* out = (float*)d_out;

    float *pA, *pB;
    __half* pimg;
    cudaGetSymbolAddress((void**)&pA, g_actA);
    cudaGetSymbolAddress((void**)&pB, g_actB);
    cudaGetSymbolAddress((void**)&pimg, g_wimg);

    cudaFuncSetAttribute(wnet_mma, cudaFuncAttributeMaxDynamicSharedMemorySize, SM_TOTAL);

    transpose_x<<<dim3(T_LEN / 32, CRES / 32, BATCH), dim3(32, 8)>>>(x, pA);
    prep_weights<<<dim3(NBLK, 5), 256>>>(w_dil, w_res, w_skip, pimg);

    for (int i = 0; i < NBLK; ++i) {
        const float* srcp = (i & 1) ? pB : pA;
        float* dstp       = (i & 1) ? pA : pB;
        wnet_mma<<<dim3(T_LEN / TT, BATCH), THREADS, SM_TOTAL>>>(
            srcp, dstp,
            pimg + (size_t)i * 10 * 16384,
            out + (size_t)i * BATCH * 256 * SKIPLEN,
            1 << (i % 10));
    }
}

// round 7
// speedup vs baseline: 3.5201x; 1.0681x over previous
#include <cuda_runtime.h>
#include <cuda_fp16.h>
#include <cstdint>

#define T_LEN 16384
#define BATCH 4
#define CRES 128
#define NBLK 40
#define SKIPLEN 4096
#define SKIPSTART (T_LEN - SKIPLEN)

#define THREADS 256
#define TT 64

// SMEM layout (bytes) — XOR-swizzled, zero padding
#define SM_XD  0            // 64 rows x 256B fp16 (Xd, later G)
#define SM_XC  16384        // 64 rows x 256B fp16 (Xc)
#define SM_W0  32768        // 32KB image buffer 0
#define SM_W1  65536        // 32KB image buffer 1
#define SM_TOTAL 98304

// ---------------- device scratch ----------------
__device__ float g_actA[(size_t)BATCH * T_LEN * CRES];
__device__ float g_actB[(size_t)BATCH * T_LEN * CRES];
// per block: 10 images of 128x128 fp16 row-major [o][k], in TERM order:
// 0=wd0hi 1=wd0lo 2=wd1hi 3=wd1lo 4=wreshi 5=wreslo 6=wskAhi 7=wskAlo 8=wskBhi 9=wskBlo
__device__ __align__(16) __half g_wimg[(size_t)NBLK * 10 * 16384];

// ---------------- helpers ----------------
__device__ __forceinline__ uint32_t smem_u32(const void* p) {
    uint32_t a;
    asm("{ .reg .u64 t; cvta.to.shared.u64 t, %1; cvt.u32.u64 %0, t; }" : "=r"(a) : "l"(p));
    return a;
}
__device__ __forceinline__ void ldsm4(uint32_t* r, uint32_t addr) {
    asm volatile("ldmatrix.sync.aligned.m8n8.x4.shared.b16 {%0,%1,%2,%3}, [%4];"
                 : "=r"(r[0]), "=r"(r[1]), "=r"(r[2]), "=r"(r[3]) : "r"(addr));
}
__device__ __forceinline__ void mma16816(float* d, const uint32_t* a, const uint32_t* b) {
    asm volatile("mma.sync.aligned.m16n8k16.row.col.f32.f16.f16.f32 "
                 "{%0,%1,%2,%3},{%4,%5,%6,%7},{%8,%9},{%0,%1,%2,%3};"
                 : "+f"(d[0]), "+f"(d[1]), "+f"(d[2]), "+f"(d[3])
                 : "r"(a[0]), "r"(a[1]), "r"(a[2]), "r"(a[3]), "r"(b[0]), "r"(b[1]));
}
__device__ __forceinline__ void cpa16(uint32_t dst, const void* src) {
    asm volatile("cp.async.cg.shared.global [%0], [%1], 16;" :: "r"(dst), "l"(src));
}
#define CP_COMMIT()  asm volatile("cp.async.commit_group;" ::: "memory")
#define CP_WAITG(n)  asm volatile("cp.async.wait_group %0;" :: "n"(n) : "memory")

__device__ __forceinline__ uint32_t pack_h2(float x0, float x1) {
    __half2 h = __floats2half2_rn(x0, x1);
    return *reinterpret_cast<uint32_t*>(&h);
}
__device__ __forceinline__ float gate_fn(float h) {
    h = fminf(fmaxf(h, -30.f), 30.f);
    float e = __expf(-h);
    float e2 = e * e;
    return __fdividef(1.f - e2, (1.f + e2) * (1.f + e));
}

// ---------------- pre-pass kernels ----------------
__global__ void transpose_x(const float* __restrict__ x, float* __restrict__ xt) {
    __shared__ float tile[32][33];
    int b = blockIdx.z, c0 = blockIdx.y * 32, t0 = blockIdx.x * 32;
    int lx = threadIdx.x, ly = threadIdx.y;
    #pragma unroll
    for (int i = 0; i < 32; i += 8)
        tile[ly + i][lx] = x[((size_t)b * CRES + c0 + ly + i) * T_LEN + t0 + lx];
    __syncthreads();
    #pragma unroll
    for (int i = 0; i < 32; i += 8)
        xt[((size_t)b * T_LEN + t0 + ly + i) * CRES + c0 + lx] = tile[lx][ly + i];
}

__global__ void prep_weights(const float* __restrict__ wd, const float* __restrict__ wr,
                             const float* __restrict__ wsk, __half* __restrict__ img) {
    int blk = blockIdx.x, m = blockIdx.y;
    for (int e = threadIdx.x; e < 16384; e += 256) {
        int o = e >> 7, k = e & 127;
        float v;
        if      (m == 0) v = wd[((size_t)blk * 16384 + o * 128 + k) * 2 + 0];
        else if (m == 1) v = wd[((size_t)blk * 16384 + o * 128 + k) * 2 + 1];
        else if (m == 2) v = wr[(size_t)blk * 16384 + o * 128 + k];
        else if (m == 3) v = wsk[(size_t)blk * 32768 + o * 128 + k];
        else             v = wsk[(size_t)blk * 32768 + (o + 128) * 128 + k];
        __half hi = __float2half_rn(v);
        __half lo = __float2half_rn(v - __half2float(hi));
        size_t base = ((size_t)blk * 10 + (size_t)m * 2) * 16384;
        img[base + e] = hi;
        img[base + 16384 + e] = lo;
    }
}

// ---------------- main block kernel ----------------
__global__ void __launch_bounds__(THREADS, 2)
wnet_mma(const float* __restrict__ in, float* __restrict__ resout,
         const __half* __restrict__ img, float* __restrict__ skipout, int dil)
{
    extern __shared__ char smem[];
    const uint32_t sb = smem_u32(smem);
    const int tid = threadIdx.x;
    const int lane = tid & 31, wid = tid >> 5;
    const int wm = wid & 1;        // 2 M groups (32 t rows each)
    const int wn = wid >> 1;       // 4 N groups (32 out cols each)
    const int b = blockIdx.y, t0 = blockIdx.x * TT;
    const bool skip = (t0 >= SKIPSTART);

    // per-lane ldmatrix constants (swizzled, 256B rows / 16 chunks)
    const uint32_t arow = (uint32_t)(wm * 32 + (lane & 15)) * 256;
    const uint32_t rxa  = (uint32_t)(lane & 7) << 4;
    const uint32_t kla  = (uint32_t)(lane >> 4) << 4;
    const uint32_t brow = (uint32_t)(wn * 32 + (lane & 7) + ((lane >> 4) << 3)) * 256;
    const uint32_t rxb  = (uint32_t)(lane & 7) << 4;
    const uint32_t klb  = (uint32_t)((lane >> 3) & 1) << 4;

    const float* src = in + (size_t)b * T_LEN * CRES;

    // ---- single 32KB image load (row-major -> swizzled SMEM), one commit group ----
    auto load_img = [&](int term, uint32_t wb) {
        const char* g = (const char*)(img + (size_t)term * 16384);
        #pragma unroll
        for (int i = 0; i < 8; ++i) {
            uint32_t e = (uint32_t)tid + i * THREADS;      // 0..2047 16B chunks
            uint32_t row = e >> 4, k = e & 15;
            cpa16(sb + wb + row * 256 + ((k ^ (row & 7)) << 4), g + (size_t)e * 16);
        }
        CP_COMMIT();
    };

    // ---- activation tile load -> fp16 slot ----
    auto load_half = [&](int slot, bool shifted) {
        int row = tid >> 2, q = tid & 3;
        int ts = shifted ? (t0 + row - dil) : (t0 + row);
        bool valid = ts >= 0;
        const float* rp = src + (size_t)(valid ? ts : 0) * CRES + q * 32;
        uint32_t rbase = (uint32_t)row * 256;
        uint32_t rw = (uint32_t)(row & 7);
        #pragma unroll
        for (int j = 0; j < 8; ++j) {
            float4 v = valid ? *(const float4*)(rp + j * 4) : make_float4(0.f, 0.f, 0.f, 0.f);
            uint32_t chunk = (uint32_t)q * 4 + (j >> 1);
            uint32_t off = rbase + ((chunk ^ rw) << 4) + (j & 1) * 8;
            *(uint32_t*)(smem + slot + off)     = pack_h2(v.x, v.y);
            *(uint32_t*)(smem + slot + off + 4) = pack_h2(v.z, v.w);
        }
    };

    float acc[2][4][4];
    auto zero_acc = [&]() {
        #pragma unroll
        for (int mt = 0; mt < 2; ++mt)
            #pragma unroll
            for (int nt = 0; nt < 4; ++nt)
                #pragma unroll
                for (int j = 0; j < 4; ++j) acc[mt][nt][j] = 0.f;
    };

    // ---- one single-image GEMM term: acc += A x W^T ----
    auto gemm1 = [&](uint32_t aSlot, uint32_t wb) {
        #pragma unroll
        for (int k0 = 0; k0 < 8; ++k0) {
            uint32_t aoffs = (((uint32_t)k0 * 32 + kla) ^ rxa);
            uint32_t boffs = (((uint32_t)k0 * 32 + klb) ^ rxb);
            uint32_t a[2][4], bb[2][4];
            ldsm4(a[0], sb + aSlot + arow + aoffs);
            ldsm4(a[1], sb + aSlot + arow + 4096 + aoffs);
            ldsm4(bb[0], sb + wb + brow + boffs);
            ldsm4(bb[1], sb + wb + brow + 4096 + boffs);
            #pragma unroll
            for (int mt = 0; mt < 2; ++mt)
                #pragma unroll
                for (int nt = 0; nt < 4; ++nt)
                    mma16816(acc[mt][nt], a[mt], &bb[nt >> 1][(nt & 1) * 2]);
        }
    };

    // ---- skip bounce staging into a dead 32KB W buffer, layout [o][t] swizzled ----
    auto stage_bounce = [&](uint32_t bbuf) {
        #pragma unroll
        for (int mt = 0; mt < 2; ++mt)
            #pragma unroll
            for (int nt = 0; nt < 4; ++nt) {
                int c = wn * 32 + nt * 8 + (lane & 3) * 2;
                #pragma unroll
                for (int h = 0; h < 2; ++h) {
                    int r = wm * 32 + mt * 16 + (lane >> 2) + h * 8;
                    uint32_t sw = ((uint32_t)(r >> 2) ^ (uint32_t)(c & 7)) << 4;
                    *(float*)(smem + bbuf + (uint32_t)c * 256 + sw + (r & 3) * 4)
                        = acc[mt][nt][h * 2 + 0];
                    uint32_t sw2 = ((uint32_t)(r >> 2) ^ (uint32_t)((c + 1) & 7)) << 4;
                    *(float*)(smem + bbuf + (uint32_t)(c + 1) * 256 + sw2 + (r & 3) * 4)
                        = acc[mt][nt][h * 2 + 1];
                }
            }
    };
    auto write_bounce = [&](uint32_t bbuf, int half) {
        float* sd = skipout + ((size_t)b * 256 + half * 128) * SKIPLEN + (t0 - SKIPSTART);
        #pragma unroll
        for (int p = 0; p < 4; ++p) {
            int o = p * 32 + wid * 4 + (lane >> 3);
            int f = lane & 7;
            #pragma unroll
            for (int q = 0; q < 2; ++q) {
                int ch = f + q * 8;
                float4 v = *(float4*)(smem + bbuf + (uint32_t)o * 256
                                      + (((uint32_t)ch ^ (uint32_t)(o & 7)) << 4));
                *(float4*)(sd + (size_t)o * SKIPLEN + ch * 4) = v;
            }
        }
    };

    // ================= prologue =================
    load_img(0, SM_W0);
    load_img(1, SM_W1);
    load_half(SM_XD, true);
    load_half(SM_XC, false);
    CP_WAITG(1);
    __syncthreads();

    zero_acc();
    gemm1(SM_XD, SM_W0);                 // T0: wd0 hi
    CP_WAITG(0); __syncthreads(); load_img(2, SM_W0);
    gemm1(SM_XD, SM_W1);                 // T1: wd0 lo
    CP_WAITG(0); __syncthreads(); load_img(3, SM_W1);
    gemm1(SM_XC, SM_W0);                 // T2: wd1 hi
    CP_WAITG(0); __syncthreads(); load_img(4, SM_W0);
    gemm1(SM_XC, SM_W1);                 // T3: wd1 lo

    // ---- gate -> G into XD slot ----
    #pragma unroll
    for (int mt = 0; mt < 2; ++mt)
        #pragma unroll
        for (int nt = 0; nt < 4; ++nt) {
            int c = wn * 32 + nt * 8 + (lane & 3) * 2;
            #pragma unroll
            for (int h = 0; h < 2; ++h) {
                int r = wm * 32 + mt * 16 + (lane >> 2) + h * 8;
                float g0 = gate_fn(acc[mt][nt][h * 2 + 0]);
                float g1 = gate_fn(acc[mt][nt][h * 2 + 1]);
                uint32_t off = (uint32_t)r * 256
                             + (uint32_t)((((c >> 3) ^ (r & 7)) << 4) + (c & 7) * 2);
                *(uint32_t*)(smem + SM_XD + off) = pack_h2(g0, g1);
            }
        }
    zero_acc();
    CP_WAITG(0); __syncthreads(); load_img(5, SM_W1);
    gemm1(SM_XD, SM_W0);                 // T4: wres hi
    CP_WAITG(0); __syncthreads(); if (skip) load_img(6, SM_W0);
    gemm1(SM_XD, SM_W1);                 // T5: wres lo

    // ---- residual epilogue: out = acc + Xc(global fp32) ----
    {
        float* dst = resout + ((size_t)b * T_LEN + t0) * CRES;
        const float* xc = src + (size_t)t0 * CRES;
        #pragma unroll
        for (int mt = 0; mt < 2; ++mt)
            #pragma unroll
            for (int nt = 0; nt < 4; ++nt) {
                int c = wn * 32 + nt * 8 + (lane & 3) * 2;
                #pragma unroll
                for (int h = 0; h < 2; ++h) {
                    int r = wm * 32 + mt * 16 + (lane >> 2) + h * 8;
                    float2 x = *(const float2*)(xc + (size_t)r * CRES + c);
                    float2 o;
                    o.x = acc[mt][nt][h * 2 + 0] + x.x;
                    o.y = acc[mt][nt][h * 2 + 1] + x.y;
                    *(float2*)(dst + (size_t)r * CRES + c) = o;
                }
            }
    }
    if (!skip) return;

    // ================= skip phase =================
    CP_WAITG(0); __syncthreads(); load_img(7, SM_W1);
    zero_acc();
    gemm1(SM_XD, SM_W0);                 // T6: wskA hi
    CP_WAITG(0); __syncthreads(); load_img(8, SM_W0);
    gemm1(SM_XD, SM_W1);                 // T7: wskA lo
    CP_WAITG(0); __syncthreads();        // T8 resident; W1 consumed -> bounce
    stage_bounce(SM_W1);
    __syncthreads();
    write_bounce(SM_W1, 0);
    __syncthreads();
    load_img(9, SM_W1);
    zero_acc();
    gemm1(SM_XD, SM_W0);                 // T8: wskB hi
    CP_WAITG(0); __syncthreads();
    gemm1(SM_XD, SM_W1);                 // T9: wskB lo
    __syncthreads();                     // W0 consumed -> bounce
    stage_bounce(SM_W0);
    __syncthreads();
    write_bounce(SM_W0, 1);
}

// ---------------- host ----------------
extern "C" void kernel_launch(void* const* d_in, const int* in_sizes, int n_in,
                              void* d_out, int out_size)
{
    const float* x      = (const float*)d_in[0];
    const float* w_dil  = (const float*)d_in[1];
    const float* w_res  = (const float*)d_in[2];
    const float* w_skip = (const float*)d_in[3];
    float* out = (float*)d_out;

    float *pA, *pB;
    __half* pimg;
    cudaGetSymbolAddress((void**)&pA, g_actA);
    cudaGetSymbolAddress((void**)&pB, g_actB);
    cudaGetSymbolAddress((void**)&pimg, g_wimg);

    cudaFuncSetAttribute(wnet_mma, cudaFuncAttributeMaxDynamicSharedMemorySize, SM_TOTAL);

    transpose_x<<<dim3(T_LEN / 32, CRES / 32, BATCH), dim3(32, 8)>>>(x, pA);
    prep_weights<<<dim3(NBLK, 5), 256>>>(w_dil, w_res, w_skip, pimg);

    for (int i = 0; i < NBLK; ++i) {
        const float* srcp = (i & 1) ? pB : pA;
        float* dstp       = (i & 1) ? pA : pB;
        wnet_mma<<<dim3(T_LEN / TT, BATCH), THREADS, SM_TOTAL>>>(
            srcp, dstp,
            pimg + (size_t)i * 10 * 16384,
            out + (size_t)i * BATCH * 256 * SKIPLEN,
            1 << (i % 10));
    }
}

// round 8
// speedup vs baseline: 3.8416x; 1.0913x over previous
#include <cuda_runtime.h>
#include <cuda_fp16.h>
#include <cstdint>

#define T_LEN 16384
#define BATCH 4
#define CRES 128
#define NBLK 40
#define SKIPLEN 4096
#define SKIPSTART (T_LEN - SKIPLEN)

#define THREADS 256
#define TT 64

// SMEM layout (bytes) — XOR-swizzled, zero padding
#define SM_XD  0            // 64 rows x 256B fp16 (Xd, later G)
#define SM_XC  16384        // 64 rows x 256B fp16 (Xc)
#define SM_W0  32768        // 32KB chunk buffer 0 (hi-half @0, lo-half @16384; 128B rows)
#define SM_W1  65536        // 32KB chunk buffer 1
#define SM_TOTAL 98304

// ---------------- device scratch ----------------
__device__ float g_actA[(size_t)BATCH * T_LEN * CRES];
__device__ float g_actB[(size_t)BATCH * T_LEN * CRES];
// per block: 5 matrices x 2 K-chunks; each chunk = 16KB hi-half + 16KB lo-half.
// chunk index = m*2 + c;   m: 0=wd tap0, 1=wd tap1, 2=wres, 3=wskA, 4=wskB
__device__ __align__(16) __half g_wimg[(size_t)NBLK * 10 * 16384];

// ---------------- helpers ----------------
__device__ __forceinline__ uint32_t smem_u32(const void* p) {
    uint32_t a;
    asm("{ .reg .u64 t; cvta.to.shared.u64 t, %1; cvt.u32.u64 %0, t; }" : "=r"(a) : "l"(p));
    return a;
}
__device__ __forceinline__ void ldsm4(uint32_t* r, uint32_t addr) {
    asm volatile("ldmatrix.sync.aligned.m8n8.x4.shared.b16 {%0,%1,%2,%3}, [%4];"
                 : "=r"(r[0]), "=r"(r[1]), "=r"(r[2]), "=r"(r[3]) : "r"(addr));
}
__device__ __forceinline__ void mma16816(float* d, const uint32_t* a, const uint32_t* b) {
    asm volatile("mma.sync.aligned.m16n8k16.row.col.f32.f16.f16.f32 "
                 "{%0,%1,%2,%3},{%4,%5,%6,%7},{%8,%9},{%0,%1,%2,%3};"
                 : "+f"(d[0]), "+f"(d[1]), "+f"(d[2]), "+f"(d[3])
                 : "r"(a[0]), "r"(a[1]), "r"(a[2]), "r"(a[3]), "r"(b[0]), "r"(b[1]));
}
__device__ __forceinline__ void cpa16(uint32_t dst, const void* src) {
    asm volatile("cp.async.cg.shared.global [%0], [%1], 16;" :: "r"(dst), "l"(src));
}
#define CP_COMMIT()  asm volatile("cp.async.commit_group;" ::: "memory")
#define CP_WAITG(n)  asm volatile("cp.async.wait_group %0;" :: "n"(n) : "memory")

__device__ __forceinline__ uint32_t pack_h2(float x0, float x1) {
    __half2 h = __floats2half2_rn(x0, x1);
    return *reinterpret_cast<uint32_t*>(&h);
}
__device__ __forceinline__ float gate_fn(float h) {
    h = fminf(fmaxf(h, -30.f), 30.f);
    float e = __expf(-h);
    float e2 = e * e;
    return __fdividef(1.f - e2, (1.f + e2) * (1.f + e));
}

// ---------------- pre-pass kernels ----------------
__global__ void transpose_x(const float* __restrict__ x, float* __restrict__ xt) {
    __shared__ float tile[32][33];
    int b = blockIdx.z, c0 = blockIdx.y * 32, t0 = blockIdx.x * 32;
    int lx = threadIdx.x, ly = threadIdx.y;
    #pragma unroll
    for (int i = 0; i < 32; i += 8)
        tile[ly + i][lx] = x[((size_t)b * CRES + c0 + ly + i) * T_LEN + t0 + lx];
    __syncthreads();
    #pragma unroll
    for (int i = 0; i < 32; i += 8)
        xt[((size_t)b * T_LEN + t0 + ly + i) * CRES + c0 + lx] = tile[lx][ly + i];
}

__global__ void prep_weights(const float* __restrict__ wd, const float* __restrict__ wr,
                             const float* __restrict__ wsk, __half* __restrict__ img) {
    int blk = blockIdx.x, m = blockIdx.y;
    for (int e = threadIdx.x; e < 16384; e += 256) {
        int o = e >> 7, k = e & 127;
        float v;
        if      (m == 0) v = wd[((size_t)blk * 16384 + o * 128 + k) * 2 + 0];
        else if (m == 1) v = wd[((size_t)blk * 16384 + o * 128 + k) * 2 + 1];
        else if (m == 2) v = wr[(size_t)blk * 16384 + o * 128 + k];
        else if (m == 3) v = wsk[(size_t)blk * 32768 + o * 128 + k];
        else             v = wsk[(size_t)blk * 32768 + (o + 128) * 128 + k];
        __half hi = __float2half_rn(v);
        __half lo = __float2half_rn(v - __half2float(hi));
        int c = k >> 6, kl = k & 63;
        size_t base = (size_t)blk * 163840 + (size_t)(m * 2 + c) * 16384;
        img[base + o * 64 + kl]        = hi;   // hi-half: 128 rows x 128B
        img[base + 8192 + o * 64 + kl] = lo;   // lo-half
    }
}

// ---------------- main block kernel ----------------
__global__ void __launch_bounds__(THREADS, 2)
wnet_mma(const float* __restrict__ in, float* __restrict__ resout,
         const __half* __restrict__ img, float* __restrict__ skipout, int dil)
{
    extern __shared__ char smem[];
    const uint32_t sb = smem_u32(smem);
    const int tid = threadIdx.x;
    const int lane = tid & 31, wid = tid >> 5;
    const int wm = wid & 1;        // 2 M groups (32 t rows each)
    const int wn = wid >> 1;       // 4 N groups (32 out cols each)
    const int b = blockIdx.y, t0 = blockIdx.x * TT;
    const bool skip = (t0 >= SKIPSTART);

    // A-side ldmatrix constants (256B rows, 16 chunks)
    const uint32_t arow = (uint32_t)(wm * 32 + (lane & 15)) * 256;
    const uint32_t rxa  = (uint32_t)(lane & 7) << 4;
    const uint32_t kla  = (uint32_t)(lane >> 4) << 4;
    // B-side ldmatrix constants (128B rows, 8 chunks)
    const uint32_t brow = (uint32_t)(wn * 32 + (lane & 7) + ((lane >> 4) << 3)) * 128;
    const uint32_t rxb  = (uint32_t)(lane & 7) << 4;
    const uint32_t klb  = (uint32_t)((lane >> 3) & 1) << 4;

    const float* src = in + (size_t)b * T_LEN * CRES;

    // ---- 32KB K-chunk load (hi-half + lo-half, 128B rows, swizzled) ----
    auto load_img = [&](int cidx, uint32_t wb) {
        const char* g = (const char*)(img + (size_t)cidx * 16384);
        #pragma unroll
        for (int i = 0; i < 8; ++i) {
            uint32_t e = (uint32_t)tid + i * THREADS;      // 0..2047 16B chunks
            uint32_t sec = e >> 10, ee = e & 1023;
            uint32_t row = ee >> 3, k = ee & 7;
            cpa16(sb + wb + sec * 16384 + row * 128 + ((k ^ (row & 7)) << 4),
                  g + (size_t)e * 16);
        }
        CP_COMMIT();
    };

    // ---- activation tile load -> fp16 slot (256B rows) ----
    auto load_half = [&](int slot, bool shifted) {
        int row = tid >> 2, q = tid & 3;
        int ts = shifted ? (t0 + row - dil) : (t0 + row);
        bool valid = ts >= 0;
        const float* rp = src + (size_t)(valid ? ts : 0) * CRES + q * 32;
        uint32_t rbase = (uint32_t)row * 256;
        uint32_t rw = (uint32_t)(row & 7);
        #pragma unroll
        for (int j = 0; j < 8; ++j) {
            float4 v = valid ? *(const float4*)(rp + j * 4) : make_float4(0.f, 0.f, 0.f, 0.f);
            uint32_t chunk = (uint32_t)q * 4 + (j >> 1);
            uint32_t off = rbase + ((chunk ^ rw) << 4) + (j & 1) * 8;
            *(uint32_t*)(smem + slot + off)     = pack_h2(v.x, v.y);
            *(uint32_t*)(smem + slot + off + 4) = pack_h2(v.z, v.w);
        }
    };

    float acc[2][4][4];
    auto zero_acc = [&]() {
        #pragma unroll
        for (int mt = 0; mt < 2; ++mt)
            #pragma unroll
            for (int nt = 0; nt < 4; ++nt)
                #pragma unroll
                for (int j = 0; j < 4; ++j) acc[mt][nt][j] = 0.f;
    };

    // ---- one K-chunk (K=64, hi+lo fused; A loaded once per k0) ----
    auto gemm_chunk = [&](uint32_t aSlot, uint32_t wb, int k0base) {
        #pragma unroll
        for (int k0l = 0; k0l < 4; ++k0l) {
            uint32_t aoffs = ((((uint32_t)(k0base + k0l)) * 32 + kla) ^ rxa);
            uint32_t boffs = (((uint32_t)k0l * 32 + klb) ^ rxb);
            uint32_t a[2][4], bh[2][4], bl[2][4];
            ldsm4(a[0], sb + aSlot + arow + aoffs);
            ldsm4(a[1], sb + aSlot + arow + 4096 + aoffs);
            ldsm4(bh[0], sb + wb + brow + boffs);
            ldsm4(bh[1], sb + wb + brow + 2048 + boffs);
            ldsm4(bl[0], sb + wb + 16384 + brow + boffs);
            ldsm4(bl[1], sb + wb + 16384 + brow + 2048 + boffs);
            #pragma unroll
            for (int mt = 0; mt < 2; ++mt)
                #pragma unroll
                for (int nt = 0; nt < 4; ++nt) {
                    mma16816(acc[mt][nt], a[mt], &bh[nt >> 1][(nt & 1) * 2]);
                    mma16816(acc[mt][nt], a[mt], &bl[nt >> 1][(nt & 1) * 2]);
                }
        }
    };

    // ---- skip bounce staging into a dead 32KB W buffer, layout [o][t] swizzled ----
    auto stage_bounce = [&](uint32_t bbuf) {
        #pragma unroll
        for (int mt = 0; mt < 2; ++mt)
            #pragma unroll
            for (int nt = 0; nt < 4; ++nt) {
                int c = wn * 32 + nt * 8 + (lane & 3) * 2;
                #pragma unroll
                for (int h = 0; h < 2; ++h) {
                    int r = wm * 32 + mt * 16 + (lane >> 2) + h * 8;
                    uint32_t sw = ((uint32_t)(r >> 2) ^ (uint32_t)(c & 7)) << 4;
                    *(float*)(smem + bbuf + (uint32_t)c * 256 + sw + (r & 3) * 4)
                        = acc[mt][nt][h * 2 + 0];
                    uint32_t sw2 = ((uint32_t)(r >> 2) ^ (uint32_t)((c + 1) & 7)) << 4;
                    *(float*)(smem + bbuf + (uint32_t)(c + 1) * 256 + sw2 + (r & 3) * 4)
                        = acc[mt][nt][h * 2 + 1];
                }
            }
    };
    auto write_bounce = [&](uint32_t bbuf, int half) {
        float* sd = skipout + ((size_t)b * 256 + half * 128) * SKIPLEN + (t0 - SKIPSTART);
        #pragma unroll
        for (int p = 0; p < 4; ++p) {
            int o = p * 32 + wid * 4 + (lane >> 3);
            int f = lane & 7;
            #pragma unroll
            for (int q = 0; q < 2; ++q) {
                int ch = f + q * 8;
                float4 v = *(float4*)(smem + bbuf + (uint32_t)o * 256
                                      + (((uint32_t)ch ^ (uint32_t)(o & 7)) << 4));
                *(float4*)(sd + (size_t)o * SKIPLEN + ch * 4) = v;
            }
        }
    };

    // ================= prologue =================
    load_img(0, SM_W0);
    load_img(1, SM_W1);
    load_half(SM_XD, true);
    load_half(SM_XC, false);
    CP_WAITG(1);
    __syncthreads();

    zero_acc();
    gemm_chunk(SM_XD, SM_W0, 0);         // wd0 c0
    CP_WAITG(0); __syncthreads(); load_img(2, SM_W0);
    gemm_chunk(SM_XD, SM_W1, 4);         // wd0 c1
    CP_WAITG(0); __syncthreads(); load_img(3, SM_W1);
    gemm_chunk(SM_XC, SM_W0, 0);         // wd1 c0
    CP_WAITG(0); __syncthreads(); load_img(4, SM_W0);
    gemm_chunk(SM_XC, SM_W1, 4);         // wd1 c1

    // ---- gate -> G into XD slot ----
    #pragma unroll
    for (int mt = 0; mt < 2; ++mt)
        #pragma unroll
        for (int nt = 0; nt < 4; ++nt) {
            int c = wn * 32 + nt * 8 + (lane & 3) * 2;
            #pragma unroll
            for (int h = 0; h < 2; ++h) {
                int r = wm * 32 + mt * 16 + (lane >> 2) + h * 8;
                float g0 = gate_fn(acc[mt][nt][h * 2 + 0]);
                float g1 = gate_fn(acc[mt][nt][h * 2 + 1]);
                uint32_t off = (uint32_t)r * 256
                             + (uint32_t)((((c >> 3) ^ (r & 7)) << 4) + (c & 7) * 2);
                *(uint32_t*)(smem + SM_XD + off) = pack_h2(g0, g1);
            }
        }
    zero_acc();
    CP_WAITG(0); __syncthreads(); load_img(5, SM_W1);
    gemm_chunk(SM_XD, SM_W0, 0);         // wres c0
    CP_WAITG(0); __syncthreads(); if (skip) load_img(6, SM_W0);
    gemm_chunk(SM_XD, SM_W1, 4);         // wres c1

    // ---- residual epilogue: out = acc + Xc(global fp32) ----
    {
        float* dst = resout + ((size_t)b * T_LEN + t0) * CRES;
        const float* xc = src + (size_t)t0 * CRES;
        #pragma unroll
        for (int mt = 0; mt < 2; ++mt)
            #pragma unroll
            for (int nt = 0; nt < 4; ++nt) {
                int c = wn * 32 + nt * 8 + (lane & 3) * 2;
                #pragma unroll
                for (int h = 0; h < 2; ++h) {
                    int r = wm * 32 + mt * 16 + (lane >> 2) + h * 8;
                    float2 x = *(const float2*)(xc + (size_t)r * CRES + c);
                    float2 o;
                    o.x = acc[mt][nt][h * 2 + 0] + x.x;
                    o.y = acc[mt][nt][h * 2 + 1] + x.y;
                    *(float2*)(dst + (size_t)r * CRES + c) = o;
                }
            }
    }
    if (!skip) return;

    // ================= skip phase =================
    CP_WAITG(0); __syncthreads(); load_img(7, SM_W1);
    zero_acc();
    gemm_chunk(SM_XD, SM_W0, 0);         // wskA c0
    CP_WAITG(0); __syncthreads(); load_img(8, SM_W0);
    gemm_chunk(SM_XD, SM_W1, 4);         // wskA c1
    CP_WAITG(0); __syncthreads();        // W1 consumed -> bounce
    stage_bounce(SM_W1);
    __syncthreads();
    write_bounce(SM_W1, 0);
    __syncthreads();
    load_img(9, SM_W1);
    zero_acc();
    gemm_chunk(SM_XD, SM_W0, 0);         // wskB c0
    CP_WAITG(0); __syncthreads();
    gemm_chunk(SM_XD, SM_W1, 4);         // wskB c1
    __syncthreads();                     // W0 consumed -> bounce
    stage_bounce(SM_W0);
    __syncthreads();
    write_bounce(SM_W0, 1);
}

// ---------------- host ----------------
extern "C" void kernel_launch(void* const* d_in, const int* in_sizes, int n_in,
                              void* d_out, int out_size)
{
    const float* x      = (const float*)d_in[0];
    const float* w_dil  = (const float*)d_in[1];
    const float* w_res  = (const float*)d_in[2];
    const float* w_skip = (const float*)d_in[3];
    float* out = (float*)d_out;

    float *pA, *pB;
    __half* pimg;
    cudaGetSymbolAddress((void**)&pA, g_actA);
    cudaGetSymbolAddress((void**)&pB, g_actB);
    cudaGetSymbolAddress((void**)&pimg, g_wimg);

    cudaFuncSetAttribute(wnet_mma, cudaFuncAttributeMaxDynamicSharedMemorySize, SM_TOTAL);

    transpose_x<<<dim3(T_LEN / 32, CRES / 32, BATCH), dim3(32, 8)>>>(x, pA);
    prep_weights<<<dim3(NBLK, 5), 256>>>(w_dil, w_res, w_skip, pimg);

    for (int i = 0; i < NBLK; ++i) {
        const float* srcp = (i & 1) ? pB : pA;
        float* dstp       = (i & 1) ? pA : pB;
        wnet_mma<<<dim3(T_LEN / TT, BATCH), THREADS, SM_TOTAL>>>(
            srcp, dstp,
            pimg + (size_t)i * 163840,
            out + (size_t)i * BATCH * 256 * SKIPLEN,
            1 << (i % 10));
    }
}

// round 9
// speedup vs baseline: 4.5810x; 1.1925x over previous
#include <cuda_runtime.h>
#include <cuda_fp16.h>
#include <cstdint>

#define T_LEN 16384
#define BATCH 4
#define CRES 128
#define NBLK 40
#define SKIPLEN 4096
#define SKIPSTART (T_LEN - SKIPLEN)

#define THREADS 256
#define TT 64

// SMEM layout (bytes) — XOR-swizzled, zero padding
#define SM_XD  0            // 64 rows x 256B fp16 (Xd, later G)
#define SM_XC  16384        // 64 rows x 256B fp16 (Xc)
#define SM_W0  32768        // 16KB K-chunk buffer 0 (128 rows x 128B)
#define SM_W1  49152        // 16KB K-chunk buffer 1
#define SM_TOTAL 65536

// ---------------- device scratch ----------------
__device__ float g_actA[(size_t)BATCH * T_LEN * CRES];
__device__ float g_actB[(size_t)BATCH * T_LEN * CRES];
// per block: 5 matrices x 2 K-chunks x 8192 fp16 (16KB).
// chunk index = m*2 + c;  m: 0=wd tap0, 1=wd tap1, 2=wres, 3=wskA, 4=wskB
__device__ __align__(16) __half g_wimg[(size_t)NBLK * 10 * 8192];

// ---------------- helpers ----------------
__device__ __forceinline__ uint32_t smem_u32(const void* p) {
    uint32_t a;
    asm("{ .reg .u64 t; cvta.to.shared.u64 t, %1; cvt.u32.u64 %0, t; }" : "=r"(a) : "l"(p));
    return a;
}
__device__ __forceinline__ void ldsm4(uint32_t* r, uint32_t addr) {
    asm volatile("ldmatrix.sync.aligned.m8n8.x4.shared.b16 {%0,%1,%2,%3}, [%4];"
                 : "=r"(r[0]), "=r"(r[1]), "=r"(r[2]), "=r"(r[3]) : "r"(addr));
}
__device__ __forceinline__ void mma16816(float* d, const uint32_t* a, const uint32_t* b) {
    asm volatile("mma.sync.aligned.m16n8k16.row.col.f32.f16.f16.f32 "
                 "{%0,%1,%2,%3},{%4,%5,%6,%7},{%8,%9},{%0,%1,%2,%3};"
                 : "+f"(d[0]), "+f"(d[1]), "+f"(d[2]), "+f"(d[3])
                 : "r"(a[0]), "r"(a[1]), "r"(a[2]), "r"(a[3]), "r"(b[0]), "r"(b[1]));
}
__device__ __forceinline__ void cpa16(uint32_t dst, const void* src) {
    asm volatile("cp.async.cg.shared.global [%0], [%1], 16;" :: "r"(dst), "l"(src));
}
#define CP_COMMIT()  asm volatile("cp.async.commit_group;" ::: "memory")
#define CP_WAITG(n)  asm volatile("cp.async.wait_group %0;" :: "n"(n) : "memory")

__device__ __forceinline__ uint32_t pack_h2(float x0, float x1) {
    __half2 h = __floats2half2_rn(x0, x1);
    return *reinterpret_cast<uint32_t*>(&h);
}
__device__ __forceinline__ float gate_fn(float h) {
    h = fminf(fmaxf(h, -30.f), 30.f);
    float e = __expf(-h);
    float e2 = e * e;
    return __fdividef(1.f - e2, (1.f + e2) * (1.f + e));
}

// ---------------- pre-pass kernels ----------------
__global__ void transpose_x(const float* __restrict__ x, float* __restrict__ xt) {
    __shared__ float tile[32][33];
    int b = blockIdx.z, c0 = blockIdx.y * 32, t0 = blockIdx.x * 32;
    int lx = threadIdx.x, ly = threadIdx.y;
    #pragma unroll
    for (int i = 0; i < 32; i += 8)
        tile[ly + i][lx] = x[((size_t)b * CRES + c0 + ly + i) * T_LEN + t0 + lx];
    __syncthreads();
    #pragma unroll
    for (int i = 0; i < 32; i += 8)
        xt[((size_t)b * T_LEN + t0 + ly + i) * CRES + c0 + lx] = tile[lx][ly + i];
}

__global__ void prep_weights(const float* __restrict__ wd, const float* __restrict__ wr,
                             const float* __restrict__ wsk, __half* __restrict__ img) {
    int blk = blockIdx.x, m = blockIdx.y;
    for (int e = threadIdx.x; e < 16384; e += 256) {
        int o = e >> 7, k = e & 127;
        float v;
        if      (m == 0) v = wd[((size_t)blk * 16384 + o * 128 + k) * 2 + 0];
        else if (m == 1) v = wd[((size_t)blk * 16384 + o * 128 + k) * 2 + 1];
        else if (m == 2) v = wr[(size_t)blk * 16384 + o * 128 + k];
        else if (m == 3) v = wsk[(size_t)blk * 32768 + o * 128 + k];
        else             v = wsk[(size_t)blk * 32768 + (o + 128) * 128 + k];
        int c = k >> 6, kl = k & 63;
        size_t base = (size_t)blk * 81920 + (size_t)(m * 2 + c) * 8192;
        img[base + o * 64 + kl] = __float2half_rn(v);
    }
}

// ---------------- main block kernel ----------------
__global__ void __launch_bounds__(THREADS, 3)
wnet_mma(const float* __restrict__ in, float* __restrict__ resout,
         const __half* __restrict__ img, float* __restrict__ skipout, int dil)
{
    extern __shared__ char smem[];
    const uint32_t sb = smem_u32(smem);
    const int tid = threadIdx.x;
    const int lane = tid & 31, wid = tid >> 5;
    const int wm = wid & 1;        // 2 M groups (32 t rows each)
    const int wn = wid >> 1;       // 4 N groups (32 out cols each)
    const int b = blockIdx.y, t0 = blockIdx.x * TT;
    const bool skip = (t0 >= SKIPSTART);

    // A-side ldmatrix constants (256B rows, 16 chunks)
    const uint32_t arow = (uint32_t)(wm * 32 + (lane & 15)) * 256;
    const uint32_t rxa  = (uint32_t)(lane & 7) << 4;
    const uint32_t kla  = (uint32_t)(lane >> 4) << 4;
    // B-side ldmatrix constants (128B rows, 8 chunks)
    const uint32_t brow = (uint32_t)(wn * 32 + (lane & 7) + ((lane >> 4) << 3)) * 128;
    const uint32_t rxb  = (uint32_t)(lane & 7) << 4;
    const uint32_t klb  = (uint32_t)((lane >> 3) & 1) << 4;

    const float* src = in + (size_t)b * T_LEN * CRES;

    // ---- 16KB K-chunk load (128 rows x 128B, swizzled) ----
    auto load_img = [&](int cidx, uint32_t wb) {
        const char* g = (const char*)(img + (size_t)cidx * 8192);
        #pragma unroll
        for (int i = 0; i < 4; ++i) {
            uint32_t e = (uint32_t)tid + i * THREADS;      // 0..1023 16B chunks
            uint32_t row = e >> 3, k = e & 7;
            cpa16(sb + wb + row * 128 + ((k ^ (row & 7)) << 4), g + (size_t)e * 16);
        }
        CP_COMMIT();
    };

    // ---- activation tile load -> fp16 slot (256B rows) ----
    auto load_half = [&](int slot, bool shifted) {
        int row = tid >> 2, q = tid & 3;
        int ts = shifted ? (t0 + row - dil) : (t0 + row);
        bool valid = ts >= 0;
        const float* rp = src + (size_t)(valid ? ts : 0) * CRES + q * 32;
        uint32_t rbase = (uint32_t)row * 256;
        uint32_t rw = (uint32_t)(row & 7);
        #pragma unroll
        for (int j = 0; j < 8; ++j) {
            float4 v = valid ? *(const float4*)(rp + j * 4) : make_float4(0.f, 0.f, 0.f, 0.f);
            uint32_t chunk = (uint32_t)q * 4 + (j >> 1);
            uint32_t off = rbase + ((chunk ^ rw) << 4) + (j & 1) * 8;
            *(uint32_t*)(smem + slot + off)     = pack_h2(v.x, v.y);
            *(uint32_t*)(smem + slot + off + 4) = pack_h2(v.z, v.w);
        }
    };

    float acc[2][4][4];
    auto zero_acc = [&]() {
        #pragma unroll
        for (int mt = 0; mt < 2; ++mt)
            #pragma unroll
            for (int nt = 0; nt < 4; ++nt)
                #pragma unroll
                for (int j = 0; j < 4; ++j) acc[mt][nt][j] = 0.f;
    };

    // ---- one K-chunk GEMM (K=64, single weight term) ----
    auto gemm_chunk = [&](uint32_t aSlot, uint32_t wb, int k0base) {
        #pragma unroll
        for (int k0l = 0; k0l < 4; ++k0l) {
            uint32_t aoffs = ((((uint32_t)(k0base + k0l)) * 32 + kla) ^ rxa);
            uint32_t boffs = (((uint32_t)k0l * 32 + klb) ^ rxb);
            uint32_t a[2][4], bb[2][4];
            ldsm4(a[0], sb + aSlot + arow + aoffs);
            ldsm4(a[1], sb + aSlot + arow + 4096 + aoffs);
            ldsm4(bb[0], sb + wb + brow + boffs);
            ldsm4(bb[1], sb + wb + brow + 2048 + boffs);
            #pragma unroll
            for (int mt = 0; mt < 2; ++mt)
                #pragma unroll
                for (int nt = 0; nt < 4; ++nt)
                    mma16816(acc[mt][nt], a[mt], &bb[nt >> 1][(nt & 1) * 2]);
        }
    };

    // ---- direct skip store: acc -> skipout[o][t], 32B segments ----
    auto store_skip = [&](int half) {
        float* sd = skipout + ((size_t)b * 256 + half * 128) * SKIPLEN + (t0 - SKIPSTART);
        #pragma unroll
        for (int mt = 0; mt < 2; ++mt)
            #pragma unroll
            for (int nt = 0; nt < 4; ++nt) {
                int c = wn * 32 + nt * 8 + (lane & 3) * 2;
                #pragma unroll
                for (int h = 0; h < 2; ++h) {
                    int r = wm * 32 + mt * 16 + (lane >> 2) + h * 8;
                    sd[(size_t)c * SKIPLEN + r]       = acc[mt][nt][h * 2 + 0];
                    sd[(size_t)(c + 1) * SKIPLEN + r] = acc[mt][nt][h * 2 + 1];
                }
            }
    };

    // ================= prologue =================
    load_img(0, SM_W0);
    load_img(1, SM_W1);
    load_half(SM_XD, true);
    load_half(SM_XC, false);
    CP_WAITG(1);
    __syncthreads();

    zero_acc();
    gemm_chunk(SM_XD, SM_W0, 0);         // wd0 c0
    CP_WAITG(0); __syncthreads(); load_img(2, SM_W0);
    gemm_chunk(SM_XD, SM_W1, 4);         // wd0 c1
    CP_WAITG(0); __syncthreads(); load_img(3, SM_W1);
    gemm_chunk(SM_XC, SM_W0, 0);         // wd1 c0
    CP_WAITG(0); __syncthreads(); load_img(4, SM_W0);
    gemm_chunk(SM_XC, SM_W1, 4);         // wd1 c1

    // ---- gate -> G into XD slot ----
    #pragma unroll
    for (int mt = 0; mt < 2; ++mt)
        #pragma unroll
        for (int nt = 0; nt < 4; ++nt) {
            int c = wn * 32 + nt * 8 + (lane & 3) * 2;
            #pragma unroll
            for (int h = 0; h < 2; ++h) {
                int r = wm * 32 + mt * 16 + (lane >> 2) + h * 8;
                float g0 = gate_fn(acc[mt][nt][h * 2 + 0]);
                float g1 = gate_fn(acc[mt][nt][h * 2 + 1]);
                uint32_t off = (uint32_t)r * 256
                             + (uint32_t)((((c >> 3) ^ (r & 7)) << 4) + (c & 7) * 2);
                *(uint32_t*)(smem + SM_XD + off) = pack_h2(g0, g1);
            }
        }
    zero_acc();
    CP_WAITG(0); __syncthreads(); load_img(5, SM_W1);
    gemm_chunk(SM_XD, SM_W0, 0);         // wres c0
    CP_WAITG(0); __syncthreads(); if (skip) load_img(6, SM_W0);
    gemm_chunk(SM_XD, SM_W1, 4);         // wres c1

    // ---- residual epilogue: out = acc + Xc(global fp32) ----
    {
        float* dst = resout + ((size_t)b * T_LEN + t0) * CRES;
        const float* xc = src + (size_t)t0 * CRES;
        #pragma unroll
        for (int mt = 0; mt < 2; ++mt)
            #pragma unroll
            for (int nt = 0; nt < 4; ++nt) {
                int c = wn * 32 + nt * 8 + (lane & 3) * 2;
                #pragma unroll
                for (int h = 0; h < 2; ++h) {
                    int r = wm * 32 + mt * 16 + (lane >> 2) + h * 8;
                    float2 x = *(const float2*)(xc + (size_t)r * CRES + c);
                    float2 o;
                    o.x = acc[mt][nt][h * 2 + 0] + x.x;
                    o.y = acc[mt][nt][h * 2 + 1] + x.y;
                    *(float2*)(dst + (size_t)r * CRES + c) = o;
                }
            }
    }
    if (!skip) return;

    // ================= skip phase =================
    CP_WAITG(0); __syncthreads(); load_img(7, SM_W1);
    zero_acc();
    gemm_chunk(SM_XD, SM_W0, 0);         // wskA c0
    CP_WAITG(0); __syncthreads(); load_img(8, SM_W0);
    gemm_chunk(SM_XD, SM_W1, 4);         // wskA c1
    store_skip(0);
    CP_WAITG(0); __syncthreads(); load_img(9, SM_W1);
    zero_acc();
    gemm_chunk(SM_XD, SM_W0, 0);         // wskB c0
    CP_WAITG(0); __syncthreads();
    gemm_chunk(SM_XD, SM_W1, 4);         // wskB c1
    store_skip(1);
}

// ---------------- host ----------------
extern "C" void kernel_launch(void* const* d_in, const int* in_sizes, int n_in,
                              void* d_out, int out_size)
{
    const float* x      = (const float*)d_in[0];
    const float* w_dil  = (const float*)d_in[1];
    const float* w_res  = (const float*)d_in[2];
    const float* w_skip = (const float*)d_in[3];
    float* out = (float*)d_out;

    float *pA, *pB;
    __half* pimg;
    cudaGetSymbolAddress((void**)&pA, g_actA);
    cudaGetSymbolAddress((void**)&pB, g_actB);
    cudaGetSymbolAddress((void**)&pimg, g_wimg);

    cudaFuncSetAttribute(wnet_mma, cudaFuncAttributeMaxDynamicSharedMemorySize, SM_TOTAL);

    transpose_x<<<dim3(T_LEN / 32, CRES / 32, BATCH), dim3(32, 8)>>>(x, pA);
    prep_weights<<<dim3(NBLK, 5), 256>>>(w_dil, w_res, w_skip, pimg);

    for (int i = 0; i < NBLK; ++i) {
        const float* srcp = (i & 1) ? pB : pA;
        float* dstp       = (i & 1) ? pA : pB;
        wnet_mma<<<dim3(T_LEN / TT, BATCH), THREADS, SM_TOTAL>>>(
            srcp, dstp,
            pimg + (size_t)i * 81920,
            out + (size_t)i * BATCH * 256 * SKIPLEN,
            1 << (i % 10));
    }
}